// round 7
// baseline (speedup 1.0000x reference)
#include <cuda_runtime.h>
#include <cuda_bf16.h>
#include <math.h>
#include <stdint.h>

#define DMODEL 512
#define DK     64
#define BATCH  8
#define SEQ    2048
#define NCHUNK 4
#define CHUNK  (SEQ / NCHUNK)   // 512 keys per split-K chunk

// Scratch (device globals — no allocation allowed)
__device__ float g_Q[BATCH * SEQ * DK];                  // pre-scaled by 1/8
__device__ float g_V[BATCH * SEQ * DK];
__device__ unsigned short g_Khi[BATCH * SEQ * DK];       // bf16 trunc of K
__device__ unsigned short g_Klo[BATCH * SEQ * DK];       // bf16 residual of K
__device__ unsigned short g_VThi[BATCH * DK * SEQ];      // V^T bf16 hi
__device__ unsigned short g_VTlo[BATCH * DK * SEQ];      // V^T bf16 lo
__device__ float g_pacc[(size_t)NCHUNK * BATCH * SEQ * DK];
__device__ float g_pl[(size_t)NCHUNK * BATCH * SEQ];

// ===================== helpers =====================
__device__ __forceinline__ uint32_t pack_hi_pair(float a, float b) {
    return __byte_perm(__float_as_uint(a), __float_as_uint(b), 0x7632);
}
__device__ __forceinline__ uint32_t pack_lo_pair(float a, float b) {
    float la = a - __uint_as_float(__float_as_uint(a) & 0xFFFF0000u);
    float lb = b - __uint_as_float(__float_as_uint(b) & 0xFFFF0000u);
    uint32_t r;
    asm("cvt.rn.bf16x2.f32 %0, %1, %2;" : "=r"(r) : "f"(lb), "f"(la));
    return r;
}
__device__ __forceinline__ unsigned short hi16(float v) {
    return (unsigned short)(__float_as_uint(v) >> 16);
}
__device__ __forceinline__ unsigned short lo16(float v) {
    float r = v - __uint_as_float(__float_as_uint(v) & 0xFFFF0000u);
    unsigned short s;
    asm("cvt.rn.bf16.f32 %0, %1;" : "=h"(s) : "f"(r));
    return s;
}
__device__ __forceinline__ void mma_bf16(float* c, const uint32_t* a,
                                         uint32_t b0, uint32_t b1) {
    asm volatile(
        "mma.sync.aligned.m16n8k16.row.col.f32.bf16.bf16.f32 "
        "{%0,%1,%2,%3}, {%4,%5,%6,%7}, {%8,%9}, {%0,%1,%2,%3};"
        : "+f"(c[0]), "+f"(c[1]), "+f"(c[2]), "+f"(c[3])
        : "r"(a[0]), "r"(a[1]), "r"(a[2]), "r"(a[3]), "r"(b0), "r"(b1));
}

// smem strides in bf16 halves: 16B-aligned rows AND conflict-free frag loads
#define KSTR 72    // K tile rows (128 x 64)
#define VSTR 136   // V^T tile rows (64 x 128)
#define XSTR 72
#define WSTR 72

// ---------------------------------------------------------------------------
// Projection via mma. 64 rows/CTA, 128 threads, 4 CTAs/SM (4 independent
// barrier domains hide fill latency). which: 0=Q (scaled), 1=K (bf16), 2=V.
// ---------------------------------------------------------------------------
__global__ __launch_bounds__(128, 4) void proj_mma_kernel(
    const float* __restrict__ Xq, const float* __restrict__ Xk, const float* __restrict__ Xv,
    const float* __restrict__ Wq, const float* __restrict__ bq,
    const float* __restrict__ Wk, const float* __restrict__ bk,
    const float* __restrict__ Wv, const float* __restrict__ bv)
{
    extern __shared__ unsigned short psm[];
    unsigned short* Xhi = psm;                  // 64*XSTR
    unsigned short* Xlo = Xhi + 64 * XSTR;
    unsigned short* Whi = Xlo + 64 * XSTR;      // 64*WSTR
    unsigned short* Wlo = Whi + 64 * WSTR;

    const int which = blockIdx.y;
    const float* __restrict__ X = (which == 0) ? Xq : (which == 1) ? Xk : Xv;
    const float* __restrict__ W = (which == 0) ? Wq : (which == 1) ? Wk : Wv;
    const float* __restrict__ bias = (which == 0) ? bq : (which == 1) ? bk : bv;

    const int row0 = blockIdx.x * 64;
    const int tid = threadIdx.x;
    const int w = tid >> 5, lane = tid & 31;
    const int qr = lane >> 2, qc = lane & 3;

    float acc[8][4];
    #pragma unroll
    for (int i = 0; i < 8; i++)
        #pragma unroll
        for (int j = 0; j < 4; j++) acc[i][j] = 0.0f;

    for (int kt = 0; kt < DMODEL / 64; kt++) {
        const int k0 = kt * 64;
        __syncthreads();
        // X tile: 64 x 64 floats, 8 float4/thread
        #pragma unroll
        for (int i = 0; i < 8; i++) {
            int f = tid + i * 128;
            int r = f >> 4, c4 = (f & 15) * 4;
            float4 xv = *reinterpret_cast<const float4*>(
                &X[(size_t)(row0 + r) * DMODEL + k0 + c4]);
            *(uint32_t*)&Xhi[r * XSTR + c4]     = pack_hi_pair(xv.x, xv.y);
            *(uint32_t*)&Xhi[r * XSTR + c4 + 2] = pack_hi_pair(xv.z, xv.w);
            *(uint32_t*)&Xlo[r * XSTR + c4]     = pack_lo_pair(xv.x, xv.y);
            *(uint32_t*)&Xlo[r * XSTR + c4 + 2] = pack_lo_pair(xv.z, xv.w);
        }
        // W tile (transposed store): 64 x 64
        #pragma unroll
        for (int i = 0; i < 8; i++) {
            int f = tid + i * 128;
            int r = f >> 4, c4 = (f & 15) * 4;   // r = k row, c4 = n col
            float4 wv = *reinterpret_cast<const float4*>(
                &W[(size_t)(k0 + r) * DK + c4]);
            Whi[(c4 + 0) * WSTR + r] = hi16(wv.x);
            Whi[(c4 + 1) * WSTR + r] = hi16(wv.y);
            Whi[(c4 + 2) * WSTR + r] = hi16(wv.z);
            Whi[(c4 + 3) * WSTR + r] = hi16(wv.w);
            Wlo[(c4 + 0) * WSTR + r] = lo16(wv.x);
            Wlo[(c4 + 1) * WSTR + r] = lo16(wv.y);
            Wlo[(c4 + 2) * WSTR + r] = lo16(wv.z);
            Wlo[(c4 + 3) * WSTR + r] = lo16(wv.w);
        }
        __syncthreads();

        #pragma unroll
        for (int kb = 0; kb < 4; kb++) {
            const int abase = (w * 16 + qr) * XSTR + kb * 16 + qc * 2;
            uint32_t ah[4], al[4];
            ah[0] = *(uint32_t*)&Xhi[abase];
            ah[1] = *(uint32_t*)&Xhi[abase + 8 * XSTR];
            ah[2] = *(uint32_t*)&Xhi[abase + 8];
            ah[3] = *(uint32_t*)&Xhi[abase + 8 * XSTR + 8];
            al[0] = *(uint32_t*)&Xlo[abase];
            al[1] = *(uint32_t*)&Xlo[abase + 8 * XSTR];
            al[2] = *(uint32_t*)&Xlo[abase + 8];
            al[3] = *(uint32_t*)&Xlo[abase + 8 * XSTR + 8];
            #pragma unroll
            for (int nb = 0; nb < 8; nb++) {
                const int boff = (nb * 8 + qr) * WSTR + kb * 16 + qc * 2;
                uint32_t bh0 = *(uint32_t*)&Whi[boff];
                uint32_t bh1 = *(uint32_t*)&Whi[boff + 8];
                uint32_t bl0 = *(uint32_t*)&Wlo[boff];
                uint32_t bl1 = *(uint32_t*)&Wlo[boff + 8];
                mma_bf16(acc[nb], ah, bh0, bh1);
                mma_bf16(acc[nb], ah, bl0, bl1);
                mma_bf16(acc[nb], al, bh0, bh1);
            }
        }
    }

    const int r0 = row0 + w * 16 + qr;
    #pragma unroll
    for (int nb = 0; nb < 8; nb++) {
        const int n = nb * 8 + qc * 2;
        float bx = bias[n], by = bias[n + 1];
        float ax = acc[nb][0] + bx, ay = acc[nb][1] + by;
        float cx = acc[nb][2] + bx, cy = acc[nb][3] + by;
        if (which == 1) {
            *(uint32_t*)&g_Khi[(size_t)r0 * DK + n]       = pack_hi_pair(ax, ay);
            *(uint32_t*)&g_Klo[(size_t)r0 * DK + n]       = pack_lo_pair(ax, ay);
            *(uint32_t*)&g_Khi[(size_t)(r0 + 8) * DK + n] = pack_hi_pair(cx, cy);
            *(uint32_t*)&g_Klo[(size_t)(r0 + 8) * DK + n] = pack_lo_pair(cx, cy);
        } else {
            float* dst = (which == 0) ? g_Q : g_V;
            const float s = (which == 0) ? 0.125f : 1.0f;
            float2 v0, v1;
            v0.x = ax * s; v0.y = ay * s;
            v1.x = cx * s; v1.y = cy * s;
            *reinterpret_cast<float2*>(&dst[(size_t)r0 * DK + n]) = v0;
            *reinterpret_cast<float2*>(&dst[(size_t)(r0 + 8) * DK + n]) = v1;
        }
    }
}

// ---------------------------------------------------------------------------
// V^T hi/lo transpose: g_V [b][s][d] float -> g_VThi/lo [b][d][s] bf16
// ---------------------------------------------------------------------------
__global__ __launch_bounds__(256) void vt_convert_kernel()
{
    __shared__ float t[128][65];
    const int b = blockIdx.y, s0 = blockIdx.x * 128;
    const int tid = threadIdx.x;
    #pragma unroll
    for (int i = 0; i < 32; i++) {
        int idx = tid + i * 256;
        int r = idx >> 6, d = idx & 63;
        t[r][d] = g_V[((size_t)b * SEQ + s0 + r) * DK + d];
    }
    __syncthreads();
    #pragma unroll
    for (int i = 0; i < 16; i++) {
        int idx = tid + i * 256;
        int d = idx >> 6, sp = idx & 63;
        float a = t[sp * 2][d], c = t[sp * 2 + 1][d];
        size_t off = ((size_t)b * DK + d) * SEQ + s0 + sp * 2;
        *(uint32_t*)&g_VThi[off] = pack_hi_pair(a, c);
        *(uint32_t*)&g_VTlo[off] = pack_lo_pair(a, c);
    }
}

// ---------------------------------------------------------------------------
// mma split-K causal attention. 64 queries/CTA (128 thr, 4 warps), 128-key
// tiles, smem fill = pure copies of preconverted bf16 hi/lo (L2-resident).
// Grid (32, NCHUNK, 8). 3 CTAs/SM target.
// ---------------------------------------------------------------------------
__global__ __launch_bounds__(128, 3) void attn_mma_kernel()
{
    extern __shared__ unsigned short asm_[];
    unsigned short* Khi = asm_;                   // 128*KSTR
    unsigned short* Klo = Khi + 128 * KSTR;
    unsigned short* Vhi = Klo + 128 * KSTR;       // V^T: 64*VSTR
    unsigned short* Vlo = Vhi + 64 * VSTR;

    const int qtile = blockIdx.x, chunk = blockIdx.y, b = blockIdx.z;
    const int q0 = qtile * 64;
    const int kbeg = chunk * CHUNK;
    if (kbeg >= q0 + 64) return;
    const int kend = min(kbeg + CHUNK, q0 + 64);
    const int ntiles = (kend - kbeg + 127) >> 7;

    const int tid = threadIdx.x;
    const int w = tid >> 5, lane = tid & 31;
    const int qr = lane >> 2, qc = lane & 3;

    // Q fragments (persistent)
    uint32_t qh[4][4], ql[4][4];
    {
        const float* Qp = g_Q + ((size_t)b * SEQ + q0 + w * 16) * DK;
        #pragma unroll
        for (int kb = 0; kb < 4; kb++) {
            const int c0 = kb * 16 + qc * 2;
            float2 x00 = *reinterpret_cast<const float2*>(&Qp[(size_t)qr * DK + c0]);
            float2 x10 = *reinterpret_cast<const float2*>(&Qp[(size_t)(qr + 8) * DK + c0]);
            float2 x01 = *reinterpret_cast<const float2*>(&Qp[(size_t)qr * DK + c0 + 8]);
            float2 x11 = *reinterpret_cast<const float2*>(&Qp[(size_t)(qr + 8) * DK + c0 + 8]);
            qh[kb][0] = pack_hi_pair(x00.x, x00.y); ql[kb][0] = pack_lo_pair(x00.x, x00.y);
            qh[kb][1] = pack_hi_pair(x10.x, x10.y); ql[kb][1] = pack_lo_pair(x10.x, x10.y);
            qh[kb][2] = pack_hi_pair(x01.x, x01.y); ql[kb][2] = pack_lo_pair(x01.x, x01.y);
            qh[kb][3] = pack_hi_pair(x11.x, x11.y); ql[kb][3] = pack_lo_pair(x11.x, x11.y);
        }
    }

    float oacc[8][4];
    #pragma unroll
    for (int i = 0; i < 8; i++)
        #pragma unroll
        for (int j = 0; j < 4; j++) oacc[i][j] = 0.0f;
    float lsum0 = 0.0f, lsum1 = 0.0f;

    const int rowlo = q0 + w * 16 + qr;
    const int rowhi = rowlo + 8;

    for (int t = 0; t < ntiles; t++) {
        const int k0 = kbeg + t * 128;
        __syncthreads();
        // K tiles: 128 rows x 64 halves = 1024 uint4 per array
        #pragma unroll
        for (int i = 0; i < 8; i++) {
            int idx = tid + i * 128;
            int row = idx >> 3, u = idx & 7;
            const size_t gsrc = ((size_t)b * SEQ + k0 + row) * DK;
            *reinterpret_cast<uint4*>(&Khi[row * KSTR + u * 8]) =
                reinterpret_cast<const uint4*>(g_Khi + gsrc)[u];
            *reinterpret_cast<uint4*>(&Klo[row * KSTR + u * 8]) =
                reinterpret_cast<const uint4*>(g_Klo + gsrc)[u];
        }
        // V^T tiles: 64 rows x 128 halves = 1024 uint4 per array
        #pragma unroll
        for (int i = 0; i < 8; i++) {
            int idx = tid + i * 128;
            int d = idx >> 4, u = idx & 15;
            const size_t gsrc = ((size_t)b * DK + d) * SEQ + k0;
            *reinterpret_cast<uint4*>(&Vhi[d * VSTR + u * 8]) =
                reinterpret_cast<const uint4*>(g_VThi + gsrc)[u];
            *reinterpret_cast<uint4*>(&Vlo[d * VSTR + u * 8]) =
                reinterpret_cast<const uint4*>(g_VTlo + gsrc)[u];
        }
        __syncthreads();

        // ---- S = Q K^T ----
        float sc[16][4];
        #pragma unroll
        for (int i = 0; i < 16; i++)
            #pragma unroll
            for (int j = 0; j < 4; j++) sc[i][j] = 0.0f;

        #pragma unroll
        for (int kb = 0; kb < 4; kb++) {
            #pragma unroll
            for (int nb = 0; nb < 16; nb++) {
                const int boff = (nb * 8 + qr) * KSTR + kb * 16 + qc * 2;
                uint32_t bh0 = *(uint32_t*)&Khi[boff];
                uint32_t bh1 = *(uint32_t*)&Khi[boff + 8];
                uint32_t bl0 = *(uint32_t*)&Klo[boff];
                uint32_t bl1 = *(uint32_t*)&Klo[boff + 8];
                mma_bf16(sc[nb], qh[kb], bh0, bh1);
                mma_bf16(sc[nb], qh[kb], bl0, bl1);
                mma_bf16(sc[nb], ql[kb], bh0, bh1);
            }
        }

        // ---- p = mask ? exp(s) : 0 ----
        #pragma unroll
        for (int nb = 0; nb < 16; nb++) {
            const int col0 = k0 + nb * 8 + qc * 2;
            float p0 = (col0     <= rowlo) ? __expf(sc[nb][0]) : 0.0f;
            float p1 = (col0 + 1 <= rowlo) ? __expf(sc[nb][1]) : 0.0f;
            float p2 = (col0     <= rowhi) ? __expf(sc[nb][2]) : 0.0f;
            float p3 = (col0 + 1 <= rowhi) ? __expf(sc[nb][3]) : 0.0f;
            lsum0 += p0 + p1;
            lsum1 += p2 + p3;
            sc[nb][0] = p0; sc[nb][1] = p1; sc[nb][2] = p2; sc[nb][3] = p3;
        }

        // ---- O += P V ----
        #pragma unroll
        for (int kb2 = 0; kb2 < 8; kb2++) {
            uint32_t pah[4], pal[4];
            pah[0] = pack_hi_pair(sc[2*kb2][0],   sc[2*kb2][1]);
            pah[1] = pack_hi_pair(sc[2*kb2][2],   sc[2*kb2][3]);
            pah[2] = pack_hi_pair(sc[2*kb2+1][0], sc[2*kb2+1][1]);
            pah[3] = pack_hi_pair(sc[2*kb2+1][2], sc[2*kb2+1][3]);
            pal[0] = pack_lo_pair(sc[2*kb2][0],   sc[2*kb2][1]);
            pal[1] = pack_lo_pair(sc[2*kb2][2],   sc[2*kb2][3]);
            pal[2] = pack_lo_pair(sc[2*kb2+1][0], sc[2*kb2+1][1]);
            pal[3] = pack_lo_pair(sc[2*kb2+1][2], sc[2*kb2+1][3]);
            #pragma unroll
            for (int db = 0; db < 8; db++) {
                const int boff = (db * 8 + qr) * VSTR + kb2 * 16 + qc * 2;
                uint32_t bh0 = *(uint32_t*)&Vhi[boff];
                uint32_t bh1 = *(uint32_t*)&Vhi[boff + 8];
                uint32_t bl0 = *(uint32_t*)&Vlo[boff];
                uint32_t bl1 = *(uint32_t*)&Vlo[boff + 8];
                mma_bf16(oacc[db], pah, bh0, bh1);
                mma_bf16(oacc[db], pah, bl0, bl1);
                mma_bf16(oacc[db], pal, bh0, bh1);
            }
        }
    }

    lsum0 += __shfl_xor_sync(0xFFFFFFFFu, lsum0, 1);
    lsum0 += __shfl_xor_sync(0xFFFFFFFFu, lsum0, 2);
    lsum1 += __shfl_xor_sync(0xFFFFFFFFu, lsum1, 1);
    lsum1 += __shfl_xor_sync(0xFFFFFFFFu, lsum1, 2);

    const size_t lbase = (size_t)(chunk * BATCH + b) * SEQ + q0 + w * 16;
    if (qc == 0) {
        g_pl[lbase + qr]     = lsum0;
        g_pl[lbase + qr + 8] = lsum1;
    }

    const size_t obase = ((size_t)(chunk * BATCH + b) * SEQ + q0 + w * 16 + qr) * DK;
    #pragma unroll
    for (int db = 0; db < 8; db++) {
        const int n = db * 8 + qc * 2;
        float2 v0, v1;
        v0.x = oacc[db][0]; v0.y = oacc[db][1];
        v1.x = oacc[db][2]; v1.y = oacc[db][3];
        *reinterpret_cast<float2*>(&g_pacc[obase + n]) = v0;
        *reinterpret_cast<float2*>(&g_pacc[obase + 8 * DK + n]) = v1;
    }
}

// ---------------------------------------------------------------------------
// Combine
// ---------------------------------------------------------------------------
__global__ __launch_bounds__(256) void combine_kernel(float* __restrict__ O)
{
    const int idx = blockIdx.x * 256 + threadIdx.x;
    const int qg = idx >> 6;
    const int d  = idx & 63;
    float sa = 0.0f, sl = 0.0f;
    #pragma unroll
    for (int c = 0; c < NCHUNK; c++) {
        sa += g_pacc[((size_t)c * BATCH * SEQ + qg) * DK + d];
        sl += g_pl[(size_t)c * BATCH * SEQ + qg];
    }
    O[idx] = sa / sl;
}

extern "C" void kernel_launch(void* const* d_in, const int* in_sizes, int n_in,
                              void* d_out, int out_size)
{
    const float* qs = (const float*)d_in[0];
    const float* ks = (const float*)d_in[1];
    const float* vs = (const float*)d_in[2];
    // d_in[3] = mask — causal structure handled analytically
    const float* Wq = (const float*)d_in[4];
    const float* bq = (const float*)d_in[5];
    const float* Wk = (const float*)d_in[6];
    const float* bk = (const float*)d_in[7];
    const float* Wv = (const float*)d_in[8];
    const float* bv = (const float*)d_in[9];
    float* out = (float*)d_out;
    (void)in_sizes; (void)n_in; (void)out_size;

    const int proj_smem = (2 * 64 * XSTR + 2 * 64 * WSTR) * 2;    // 36864 B
    const int attn_smem = (2 * 128 * KSTR + 2 * 64 * VSTR) * 2;   // 71680 B
    cudaFuncSetAttribute(proj_mma_kernel, cudaFuncAttributeMaxDynamicSharedMemorySize, proj_smem);
    cudaFuncSetAttribute(attn_mma_kernel, cudaFuncAttributeMaxDynamicSharedMemorySize, attn_smem);

    dim3 pgrid(256, 3);   // 16384/64 row tiles x {Q,K,V}
    proj_mma_kernel<<<pgrid, 128, proj_smem>>>(qs, ks, vs, Wq, bq, Wk, bk, Wv, bv);

    dim3 cgrid(SEQ / 128, BATCH);
    vt_convert_kernel<<<cgrid, 256>>>();

    dim3 agrid(SEQ / 64, NCHUNK, BATCH);
    attn_mma_kernel<<<agrid, 128, attn_smem>>>();

    combine_kernel<<<(BATCH * SEQ * DK) / 256, 256>>>(out);
}

// round 8
// speedup vs baseline: 1.1793x; 1.1793x over previous
#include <cuda_runtime.h>
#include <cuda_bf16.h>
#include <math.h>
#include <stdint.h>

#define DMODEL 512
#define DK     64
#define BATCH  8
#define SEQ    2048
#define NCHUNK 4
#define CHUNK  (SEQ / NCHUNK)   // 512 keys per split-K chunk

// Scratch (device globals — no allocation allowed)
__device__ float g_Q[BATCH * SEQ * DK];                  // pre-scaled by 1/8
__device__ float g_V[BATCH * SEQ * DK];
__device__ unsigned short g_Khi[BATCH * SEQ * DK];       // bf16 trunc of K
__device__ unsigned short g_Klo[BATCH * SEQ * DK];       // bf16 residual of K
__device__ unsigned short g_VThi[BATCH * DK * SEQ];      // V^T bf16 hi
__device__ unsigned short g_VTlo[BATCH * DK * SEQ];      // V^T bf16 lo
__device__ float g_pacc[(size_t)NCHUNK * BATCH * SEQ * DK];
__device__ float g_pl[(size_t)NCHUNK * BATCH * SEQ];

// ===================== helpers =====================
__device__ __forceinline__ uint32_t pack_hi_pair(float a, float b) {
    return __byte_perm(__float_as_uint(a), __float_as_uint(b), 0x7632);
}
__device__ __forceinline__ uint32_t pack_lo_pair(float a, float b) {
    float la = a - __uint_as_float(__float_as_uint(a) & 0xFFFF0000u);
    float lb = b - __uint_as_float(__float_as_uint(b) & 0xFFFF0000u);
    uint32_t r;
    asm("cvt.rn.bf16x2.f32 %0, %1, %2;" : "=r"(r) : "f"(lb), "f"(la));
    return r;
}
__device__ __forceinline__ unsigned short hi16(float v) {
    return (unsigned short)(__float_as_uint(v) >> 16);
}
__device__ __forceinline__ unsigned short lo16(float v) {
    float r = v - __uint_as_float(__float_as_uint(v) & 0xFFFF0000u);
    unsigned short s;
    asm("cvt.rn.bf16.f32 %0, %1;" : "=h"(s) : "f"(r));
    return s;
}
__device__ __forceinline__ void mma_bf16(float* c, const uint32_t* a,
                                         uint32_t b0, uint32_t b1) {
    asm volatile(
        "mma.sync.aligned.m16n8k16.row.col.f32.bf16.bf16.f32 "
        "{%0,%1,%2,%3}, {%4,%5,%6,%7}, {%8,%9}, {%0,%1,%2,%3};"
        : "+f"(c[0]), "+f"(c[1]), "+f"(c[2]), "+f"(c[3])
        : "r"(a[0]), "r"(a[1]), "r"(a[2]), "r"(a[3]), "r"(b0), "r"(b1));
}
// 4x 8x8 b16 fragments in one warp instruction
__device__ __forceinline__ void ldsm_x4(uint32_t* d, uint32_t saddr) {
    asm volatile("ldmatrix.sync.aligned.m8n8.x4.shared.b16 {%0,%1,%2,%3}, [%4];"
                 : "=r"(d[0]), "=r"(d[1]), "=r"(d[2]), "=r"(d[3]) : "r"(saddr));
}
__device__ __forceinline__ uint32_t smem_u32(const void* p) {
    return (uint32_t)__cvta_generic_to_shared(p);
}

// smem strides in bf16 halves: 16B-aligned rows AND conflict-free frag loads
#define KSTR 72    // K tile rows (128 x 64)
#define VSTR 136   // V^T tile rows (64 x 128)
#define XSTR 72
#define WSTR 72

// ---------------------------------------------------------------------------
// Projection via mma (identical to the 143.2us build).
// which: 0=Q (scaled 1/8, float out), 1=K (bf16 hi/lo out), 2=V (float out).
// ---------------------------------------------------------------------------
__global__ __launch_bounds__(256, 2) void proj_mma_kernel(
    const float* __restrict__ Xq, const float* __restrict__ Xk, const float* __restrict__ Xv,
    const float* __restrict__ Wq, const float* __restrict__ bq,
    const float* __restrict__ Wk, const float* __restrict__ bk,
    const float* __restrict__ Wv, const float* __restrict__ bv)
{
    extern __shared__ unsigned short psm[];
    unsigned short* Xhi = psm;
    unsigned short* Xlo = Xhi + 128 * XSTR;
    unsigned short* Whi = Xlo + 128 * XSTR;
    unsigned short* Wlo = Whi + 64 * WSTR;

    const int which = blockIdx.y;
    const float* __restrict__ X = (which == 0) ? Xq : (which == 1) ? Xk : Xv;
    const float* __restrict__ W = (which == 0) ? Wq : (which == 1) ? Wk : Wv;
    const float* __restrict__ bias = (which == 0) ? bq : (which == 1) ? bk : bv;

    const int row0 = blockIdx.x * 128;
    const int tid = threadIdx.x;
    const int w = tid >> 5, lane = tid & 31;
    const int qr = lane >> 2, qc = lane & 3;

    float acc[8][4];
    #pragma unroll
    for (int i = 0; i < 8; i++)
        #pragma unroll
        for (int j = 0; j < 4; j++) acc[i][j] = 0.0f;

    for (int kt = 0; kt < DMODEL / 64; kt++) {
        const int k0 = kt * 64;
        __syncthreads();
        #pragma unroll
        for (int i = 0; i < 8; i++) {
            int f = tid + i * 256;
            int r = f >> 4, c4 = (f & 15) * 4;
            float4 xv = *reinterpret_cast<const float4*>(
                &X[(size_t)(row0 + r) * DMODEL + k0 + c4]);
            *(uint32_t*)&Xhi[r * XSTR + c4]     = pack_hi_pair(xv.x, xv.y);
            *(uint32_t*)&Xhi[r * XSTR + c4 + 2] = pack_hi_pair(xv.z, xv.w);
            *(uint32_t*)&Xlo[r * XSTR + c4]     = pack_lo_pair(xv.x, xv.y);
            *(uint32_t*)&Xlo[r * XSTR + c4 + 2] = pack_lo_pair(xv.z, xv.w);
        }
        #pragma unroll
        for (int i = 0; i < 4; i++) {
            int f = tid + i * 256;
            int r = f >> 4, c4 = (f & 15) * 4;
            float4 wv = *reinterpret_cast<const float4*>(
                &W[(size_t)(k0 + r) * DK + c4]);
            Whi[(c4 + 0) * WSTR + r] = hi16(wv.x);
            Whi[(c4 + 1) * WSTR + r] = hi16(wv.y);
            Whi[(c4 + 2) * WSTR + r] = hi16(wv.z);
            Whi[(c4 + 3) * WSTR + r] = hi16(wv.w);
            Wlo[(c4 + 0) * WSTR + r] = lo16(wv.x);
            Wlo[(c4 + 1) * WSTR + r] = lo16(wv.y);
            Wlo[(c4 + 2) * WSTR + r] = lo16(wv.z);
            Wlo[(c4 + 3) * WSTR + r] = lo16(wv.w);
        }
        __syncthreads();

        #pragma unroll
        for (int kb = 0; kb < 4; kb++) {
            const int abase = (w * 16 + qr) * XSTR + kb * 16 + qc * 2;
            uint32_t ah[4], al[4];
            ah[0] = *(uint32_t*)&Xhi[abase];
            ah[1] = *(uint32_t*)&Xhi[abase + 8 * XSTR];
            ah[2] = *(uint32_t*)&Xhi[abase + 8];
            ah[3] = *(uint32_t*)&Xhi[abase + 8 * XSTR + 8];
            al[0] = *(uint32_t*)&Xlo[abase];
            al[1] = *(uint32_t*)&Xlo[abase + 8 * XSTR];
            al[2] = *(uint32_t*)&Xlo[abase + 8];
            al[3] = *(uint32_t*)&Xlo[abase + 8 * XSTR + 8];
            #pragma unroll
            for (int nb = 0; nb < 8; nb++) {
                const int boff = (nb * 8 + qr) * WSTR + kb * 16 + qc * 2;
                uint32_t bh0 = *(uint32_t*)&Whi[boff];
                uint32_t bh1 = *(uint32_t*)&Whi[boff + 8];
                uint32_t bl0 = *(uint32_t*)&Wlo[boff];
                uint32_t bl1 = *(uint32_t*)&Wlo[boff + 8];
                mma_bf16(acc[nb], ah, bh0, bh1);
                mma_bf16(acc[nb], ah, bl0, bl1);
                mma_bf16(acc[nb], al, bh0, bh1);
            }
        }
    }

    const int r0 = row0 + w * 16 + qr;
    #pragma unroll
    for (int nb = 0; nb < 8; nb++) {
        const int n = nb * 8 + qc * 2;
        float bx = bias[n], by = bias[n + 1];
        float ax = acc[nb][0] + bx, ay = acc[nb][1] + by;
        float cx = acc[nb][2] + bx, cy = acc[nb][3] + by;
        if (which == 1) {
            *(uint32_t*)&g_Khi[(size_t)r0 * DK + n]       = pack_hi_pair(ax, ay);
            *(uint32_t*)&g_Klo[(size_t)r0 * DK + n]       = pack_lo_pair(ax, ay);
            *(uint32_t*)&g_Khi[(size_t)(r0 + 8) * DK + n] = pack_hi_pair(cx, cy);
            *(uint32_t*)&g_Klo[(size_t)(r0 + 8) * DK + n] = pack_lo_pair(cx, cy);
        } else {
            float* dst = (which == 0) ? g_Q : g_V;
            const float s = (which == 0) ? 0.125f : 1.0f;
            float2 v0, v1;
            v0.x = ax * s; v0.y = ay * s;
            v1.x = cx * s; v1.y = cy * s;
            *reinterpret_cast<float2*>(&dst[(size_t)r0 * DK + n]) = v0;
            *reinterpret_cast<float2*>(&dst[(size_t)(r0 + 8) * DK + n]) = v1;
        }
    }
}

// ---------------------------------------------------------------------------
// V^T hi/lo transpose (identical to 143.2us build)
// ---------------------------------------------------------------------------
__global__ __launch_bounds__(256) void vt_convert_kernel()
{
    __shared__ float t[128][65];
    const int b = blockIdx.y, s0 = blockIdx.x * 128;
    const int tid = threadIdx.x;
    #pragma unroll
    for (int i = 0; i < 32; i++) {
        int idx = tid + i * 256;
        int r = idx >> 6, d = idx & 63;
        t[r][d] = g_V[((size_t)b * SEQ + s0 + r) * DK + d];
    }
    __syncthreads();
    #pragma unroll
    for (int i = 0; i < 16; i++) {
        int idx = tid + i * 256;
        int d = idx >> 6, sp = idx & 63;
        float a = t[sp * 2][d], c = t[sp * 2 + 1][d];
        size_t off = ((size_t)b * DK + d) * SEQ + s0 + sp * 2;
        *(uint32_t*)&g_VThi[off] = pack_hi_pair(a, c);
        *(uint32_t*)&g_VTlo[off] = pack_lo_pair(a, c);
    }
}

// ---------------------------------------------------------------------------
// mma split-K causal attention (R5 structure) with ldmatrix B-fragments.
// 64 queries/CTA (128 thr, 4 warps), 128-key tiles. Grid (32, NCHUNK, 8).
// ---------------------------------------------------------------------------
__global__ __launch_bounds__(128, 3) void attn_mma_kernel()
{
    extern __shared__ unsigned short asm_[];
    unsigned short* Khi = asm_;                   // 128*KSTR
    unsigned short* Klo = Khi + 128 * KSTR;
    unsigned short* Vhi = Klo + 128 * KSTR;       // V^T: 64*VSTR
    unsigned short* Vlo = Vhi + 64 * VSTR;

    const int qtile = blockIdx.x, chunk = blockIdx.y, b = blockIdx.z;
    const int q0 = qtile * 64;
    const int kbeg = chunk * CHUNK;
    if (kbeg >= q0 + 64) return;
    const int kend = min(kbeg + CHUNK, q0 + 64);
    const int ntiles = (kend - kbeg + 127) >> 7;

    const int tid = threadIdx.x;
    const int w = tid >> 5, lane = tid & 31;
    const int qr = lane >> 2, qc = lane & 3;

    // ldmatrix per-lane row/col selector (bytes):
    // lanes 0-7: frag0 rows 0-7; 8-15: frag1 (cols +16B); 16-23: frag2 (rows +8);
    // 24-31: frag3 (rows +8, cols +16B)
    const int lrow = ((lane >> 4) & 1) * 8 + (lane & 7);
    const int lcol = ((lane >> 3) & 1) * 16;
    const uint32_t k_lsel = (uint32_t)(lrow * KSTR * 2 + lcol);
    const uint32_t v_lsel = (uint32_t)(lrow * VSTR * 2 + lcol);
    const uint32_t khi_base = smem_u32(Khi) + k_lsel;
    const uint32_t klo_base = smem_u32(Klo) + k_lsel;
    const uint32_t vhi_base = smem_u32(Vhi) + v_lsel;
    const uint32_t vlo_base = smem_u32(Vlo) + v_lsel;

    // Q fragments (persistent)
    uint32_t qh[4][4], ql[4][4];
    {
        const float* Qp = g_Q + ((size_t)b * SEQ + q0 + w * 16) * DK;
        #pragma unroll
        for (int kb = 0; kb < 4; kb++) {
            const int c0 = kb * 16 + qc * 2;
            float2 x00 = *reinterpret_cast<const float2*>(&Qp[(size_t)qr * DK + c0]);
            float2 x10 = *reinterpret_cast<const float2*>(&Qp[(size_t)(qr + 8) * DK + c0]);
            float2 x01 = *reinterpret_cast<const float2*>(&Qp[(size_t)qr * DK + c0 + 8]);
            float2 x11 = *reinterpret_cast<const float2*>(&Qp[(size_t)(qr + 8) * DK + c0 + 8]);
            qh[kb][0] = pack_hi_pair(x00.x, x00.y); ql[kb][0] = pack_lo_pair(x00.x, x00.y);
            qh[kb][1] = pack_hi_pair(x10.x, x10.y); ql[kb][1] = pack_lo_pair(x10.x, x10.y);
            qh[kb][2] = pack_hi_pair(x01.x, x01.y); ql[kb][2] = pack_lo_pair(x01.x, x01.y);
            qh[kb][3] = pack_hi_pair(x11.x, x11.y); ql[kb][3] = pack_lo_pair(x11.x, x11.y);
        }
    }

    float oacc[8][4];
    #pragma unroll
    for (int i = 0; i < 8; i++)
        #pragma unroll
        for (int j = 0; j < 4; j++) oacc[i][j] = 0.0f;
    float lsum0 = 0.0f, lsum1 = 0.0f;

    const int rowlo = q0 + w * 16 + qr;
    const int rowhi = rowlo + 8;

    for (int t = 0; t < ntiles; t++) {
        const int k0 = kbeg + t * 128;
        __syncthreads();
        // K tiles: 128 rows x 64 halves = 1024 uint4 per array
        #pragma unroll
        for (int i = 0; i < 8; i++) {
            int idx = tid + i * 128;
            int row = idx >> 3, u = idx & 7;
            const size_t gsrc = ((size_t)b * SEQ + k0 + row) * DK;
            *reinterpret_cast<uint4*>(&Khi[row * KSTR + u * 8]) =
                reinterpret_cast<const uint4*>(g_Khi + gsrc)[u];
            *reinterpret_cast<uint4*>(&Klo[row * KSTR + u * 8]) =
                reinterpret_cast<const uint4*>(g_Klo + gsrc)[u];
        }
        // V^T tiles: 64 rows x 128 halves = 1024 uint4 per array
        #pragma unroll
        for (int i = 0; i < 8; i++) {
            int idx = tid + i * 128;
            int d = idx >> 4, u = idx & 15;
            const size_t gsrc = ((size_t)b * DK + d) * SEQ + k0;
            *reinterpret_cast<uint4*>(&Vhi[d * VSTR + u * 8]) =
                reinterpret_cast<const uint4*>(g_VThi + gsrc)[u];
            *reinterpret_cast<uint4*>(&Vlo[d * VSTR + u * 8]) =
                reinterpret_cast<const uint4*>(g_VTlo + gsrc)[u];
        }
        __syncthreads();

        // ---- S = Q K^T  (ldmatrix x4: 2 n-blocks per load) ----
        float sc[16][4];
        #pragma unroll
        for (int i = 0; i < 16; i++)
            #pragma unroll
            for (int j = 0; j < 4; j++) sc[i][j] = 0.0f;

        #pragma unroll
        for (int kb = 0; kb < 4; kb++) {
            #pragma unroll
            for (int pr = 0; pr < 8; pr++) {       // n-block pairs (16 keys each)
                const uint32_t off = (uint32_t)(pr * 16 * KSTR * 2 + kb * 32);
                uint32_t bh[4], bl[4];
                ldsm_x4(bh, khi_base + off);
                ldsm_x4(bl, klo_base + off);
                mma_bf16(sc[pr*2],   qh[kb], bh[0], bh[1]);
                mma_bf16(sc[pr*2],   qh[kb], bl[0], bl[1]);
                mma_bf16(sc[pr*2],   ql[kb], bh[0], bh[1]);
                mma_bf16(sc[pr*2+1], qh[kb], bh[2], bh[3]);
                mma_bf16(sc[pr*2+1], qh[kb], bl[2], bl[3]);
                mma_bf16(sc[pr*2+1], ql[kb], bh[2], bh[3]);
            }
        }

        // ---- p = mask ? exp(s) : 0 ----
        #pragma unroll
        for (int nb = 0; nb < 16; nb++) {
            const int col0 = k0 + nb * 8 + qc * 2;
            float p0 = (col0     <= rowlo) ? __expf(sc[nb][0]) : 0.0f;
            float p1 = (col0 + 1 <= rowlo) ? __expf(sc[nb][1]) : 0.0f;
            float p2 = (col0     <= rowhi) ? __expf(sc[nb][2]) : 0.0f;
            float p3 = (col0 + 1 <= rowhi) ? __expf(sc[nb][3]) : 0.0f;
            lsum0 += p0 + p1;
            lsum1 += p2 + p3;
            sc[nb][0] = p0; sc[nb][1] = p1; sc[nb][2] = p2; sc[nb][3] = p3;
        }

        // ---- O += P V  (ldmatrix x4: 2 d-blocks per load) ----
        #pragma unroll
        for (int kb2 = 0; kb2 < 8; kb2++) {
            uint32_t pah[4], pal[4];
            pah[0] = pack_hi_pair(sc[2*kb2][0],   sc[2*kb2][1]);
            pah[1] = pack_hi_pair(sc[2*kb2][2],   sc[2*kb2][3]);
            pah[2] = pack_hi_pair(sc[2*kb2+1][0], sc[2*kb2+1][1]);
            pah[3] = pack_hi_pair(sc[2*kb2+1][2], sc[2*kb2+1][3]);
            pal[0] = pack_lo_pair(sc[2*kb2][0],   sc[2*kb2][1]);
            pal[1] = pack_lo_pair(sc[2*kb2][2],   sc[2*kb2][3]);
            pal[2] = pack_lo_pair(sc[2*kb2+1][0], sc[2*kb2+1][1]);
            pal[3] = pack_lo_pair(sc[2*kb2+1][2], sc[2*kb2+1][3]);
            #pragma unroll
            for (int pr = 0; pr < 4; pr++) {       // d-block pairs (16 dims each)
                const uint32_t off = (uint32_t)(pr * 16 * VSTR * 2 + kb2 * 32);
                uint32_t bh[4], bl[4];
                ldsm_x4(bh, vhi_base + off);
                ldsm_x4(bl, vlo_base + off);
                mma_bf16(oacc[pr*2],   pah, bh[0], bh[1]);
                mma_bf16(oacc[pr*2],   pah, bl[0], bl[1]);
                mma_bf16(oacc[pr*2],   pal, bh[0], bh[1]);
                mma_bf16(oacc[pr*2+1], pah, bh[2], bh[3]);
                mma_bf16(oacc[pr*2+1], pah, bl[2], bl[3]);
                mma_bf16(oacc[pr*2+1], pal, bh[2], bh[3]);
            }
        }
    }

    lsum0 += __shfl_xor_sync(0xFFFFFFFFu, lsum0, 1);
    lsum0 += __shfl_xor_sync(0xFFFFFFFFu, lsum0, 2);
    lsum1 += __shfl_xor_sync(0xFFFFFFFFu, lsum1, 1);
    lsum1 += __shfl_xor_sync(0xFFFFFFFFu, lsum1, 2);

    const size_t lbase = (size_t)(chunk * BATCH + b) * SEQ + q0 + w * 16;
    if (qc == 0) {
        g_pl[lbase + qr]     = lsum0;
        g_pl[lbase + qr + 8] = lsum1;
    }

    const size_t obase = ((size_t)(chunk * BATCH + b) * SEQ + q0 + w * 16 + qr) * DK;
    #pragma unroll
    for (int db = 0; db < 8; db++) {
        const int n = db * 8 + qc * 2;
        float2 v0, v1;
        v0.x = oacc[db][0]; v0.y = oacc[db][1];
        v1.x = oacc[db][2]; v1.y = oacc[db][3];
        *reinterpret_cast<float2*>(&g_pacc[obase + n]) = v0;
        *reinterpret_cast<float2*>(&g_pacc[obase + 8 * DK + n]) = v1;
    }
}

// ---------------------------------------------------------------------------
// Combine
// ---------------------------------------------------------------------------
__global__ __launch_bounds__(256) void combine_kernel(float* __restrict__ O)
{
    const int idx = blockIdx.x * 256 + threadIdx.x;
    const int qg = idx >> 6;
    const int d  = idx & 63;
    float sa = 0.0f, sl = 0.0f;
    #pragma unroll
    for (int c = 0; c < NCHUNK; c++) {
        sa += g_pacc[((size_t)c * BATCH * SEQ + qg) * DK + d];
        sl += g_pl[(size_t)c * BATCH * SEQ + qg];
    }
    O[idx] = sa / sl;
}

extern "C" void kernel_launch(void* const* d_in, const int* in_sizes, int n_in,
                              void* d_out, int out_size)
{
    const float* qs = (const float*)d_in[0];
    const float* ks = (const float*)d_in[1];
    const float* vs = (const float*)d_in[2];
    // d_in[3] = mask — causal structure handled analytically
    const float* Wq = (const float*)d_in[4];
    const float* bq = (const float*)d_in[5];
    const float* Wk = (const float*)d_in[6];
    const float* bk = (const float*)d_in[7];
    const float* Wv = (const float*)d_in[8];
    const float* bv = (const float*)d_in[9];
    float* out = (float*)d_out;
    (void)in_sizes; (void)n_in; (void)out_size;

    const int proj_smem = (2 * 128 * XSTR + 2 * 64 * WSTR) * 2;   // 55296 B
    const int attn_smem = (2 * 128 * KSTR + 2 * 64 * VSTR) * 2;   // 71680 B
    cudaFuncSetAttribute(proj_mma_kernel, cudaFuncAttributeMaxDynamicSharedMemorySize, proj_smem);
    cudaFuncSetAttribute(attn_mma_kernel, cudaFuncAttributeMaxDynamicSharedMemorySize, attn_smem);

    dim3 pgrid(128, 3);
    proj_mma_kernel<<<pgrid, 256, proj_smem>>>(qs, ks, vs, Wq, bq, Wk, bk, Wv, bv);

    dim3 cgrid(SEQ / 128, BATCH);
    vt_convert_kernel<<<cgrid, 256>>>();

    dim3 agrid(SEQ / 64, NCHUNK, BATCH);
    attn_mma_kernel<<<agrid, 128, attn_smem>>>();

    combine_kernel<<<(BATCH * SEQ * DK) / 256, 256>>>(out);
}

// round 9
// speedup vs baseline: 1.1963x; 1.0144x over previous
#include <cuda_runtime.h>
#include <cuda_bf16.h>
#include <math.h>
#include <stdint.h>

#define DMODEL 512
#define DK     64
#define BATCH  8
#define SEQ    2048
#define NCHUNK 4
#define CHUNK  (SEQ / NCHUNK)   // 512 keys per split-K chunk

// Scratch (device globals — no allocation allowed)
__device__ float g_Q[BATCH * SEQ * DK];                  // pre-scaled by 1/8
__device__ float g_V[BATCH * SEQ * DK];
__device__ unsigned short g_Khi[BATCH * SEQ * DK];       // bf16 trunc of K
__device__ unsigned short g_Klo[BATCH * SEQ * DK];       // bf16 residual of K
__device__ unsigned short g_VThi[BATCH * DK * SEQ];      // V^T bf16 hi
__device__ unsigned short g_VTlo[BATCH * DK * SEQ];      // V^T bf16 lo
__device__ float g_pacc[(size_t)NCHUNK * BATCH * SEQ * DK];
__device__ float g_pl[(size_t)NCHUNK * BATCH * SEQ];

// ===================== helpers =====================
__device__ __forceinline__ uint32_t pack_hi_pair(float a, float b) {
    return __byte_perm(__float_as_uint(a), __float_as_uint(b), 0x7632);
}
__device__ __forceinline__ uint32_t pack_lo_pair(float a, float b) {
    float la = a - __uint_as_float(__float_as_uint(a) & 0xFFFF0000u);
    float lb = b - __uint_as_float(__float_as_uint(b) & 0xFFFF0000u);
    uint32_t r;
    asm("cvt.rn.bf16x2.f32 %0, %1, %2;" : "=r"(r) : "f"(lb), "f"(la));
    return r;
}
__device__ __forceinline__ unsigned short hi16(float v) {
    return (unsigned short)(__float_as_uint(v) >> 16);
}
__device__ __forceinline__ unsigned short lo16(float v) {
    float r = v - __uint_as_float(__float_as_uint(v) & 0xFFFF0000u);
    unsigned short s;
    asm("cvt.rn.bf16.f32 %0, %1;" : "=h"(s) : "f"(r));
    return s;
}
__device__ __forceinline__ void mma_bf16(float* c, const uint32_t* a,
                                         uint32_t b0, uint32_t b1) {
    asm volatile(
        "mma.sync.aligned.m16n8k16.row.col.f32.bf16.bf16.f32 "
        "{%0,%1,%2,%3}, {%4,%5,%6,%7}, {%8,%9}, {%0,%1,%2,%3};"
        : "+f"(c[0]), "+f"(c[1]), "+f"(c[2]), "+f"(c[3])
        : "r"(a[0]), "r"(a[1]), "r"(a[2]), "r"(a[3]), "r"(b0), "r"(b1));
}
// 4x 8x8 b16 fragments in one warp instruction
__device__ __forceinline__ void ldsm_x4(uint32_t* d, uint32_t saddr) {
    asm volatile("ldmatrix.sync.aligned.m8n8.x4.shared.b16 {%0,%1,%2,%3}, [%4];"
                 : "=r"(d[0]), "=r"(d[1]), "=r"(d[2]), "=r"(d[3]) : "r"(saddr));
}
__device__ __forceinline__ uint32_t smem_u32(const void* p) {
    return (uint32_t)__cvta_generic_to_shared(p);
}

// smem strides in bf16 halves: 16B-aligned rows AND conflict-free frag loads
#define KSTR 72    // K tile rows (128 x 64)
#define VSTR 136   // V^T tile rows (64 x 128)
#define XSTR 72
#define WSTR 72

// ---------------------------------------------------------------------------
// Projection via mma, ldmatrix fragment loads.
// which: 0=Q (scaled 1/8, float out), 1=K (bf16 hi/lo out), 2=V (float out).
// ---------------------------------------------------------------------------
__global__ __launch_bounds__(256, 2) void proj_mma_kernel(
    const float* __restrict__ Xq, const float* __restrict__ Xk, const float* __restrict__ Xv,
    const float* __restrict__ Wq, const float* __restrict__ bq,
    const float* __restrict__ Wk, const float* __restrict__ bk,
    const float* __restrict__ Wv, const float* __restrict__ bv)
{
    extern __shared__ unsigned short psm[];
    unsigned short* Xhi = psm;
    unsigned short* Xlo = Xhi + 128 * XSTR;
    unsigned short* Whi = Xlo + 128 * XSTR;
    unsigned short* Wlo = Whi + 64 * WSTR;

    const int which = blockIdx.y;
    const float* __restrict__ X = (which == 0) ? Xq : (which == 1) ? Xk : Xv;
    const float* __restrict__ W = (which == 0) ? Wq : (which == 1) ? Wk : Wv;
    const float* __restrict__ bias = (which == 0) ? bq : (which == 1) ? bk : bv;

    const int row0 = blockIdx.x * 128;
    const int tid = threadIdx.x;
    const int w = tid >> 5, lane = tid & 31;
    const int qr = lane >> 2, qc = lane & 3;

    // ldmatrix lane->address maps (bytes)
    // A (row-major X): reg order a0=(r0,k0) a1=(r8,k0) a2=(r0,k8) a3=(r8,k8)
    const int a_lrow = ((lane >> 3) & 1) * 8 + (lane & 7);
    const int a_lcol = ((lane >> 4) & 1) * 16;
    // B (W^T, [n][k]): reg order b0=(n0,k0) b1=(n0,k8) b2=(n8,k0) b3=(n8,k8)
    const int b_lrow = ((lane >> 4) & 1) * 8 + (lane & 7);
    const int b_lcol = ((lane >> 3) & 1) * 16;

    const uint32_t xhi_base = smem_u32(Xhi) + (uint32_t)((w * 16 + a_lrow) * XSTR * 2 + a_lcol);
    const uint32_t xlo_base = smem_u32(Xlo) + (uint32_t)((w * 16 + a_lrow) * XSTR * 2 + a_lcol);
    const uint32_t whi_base = smem_u32(Whi) + (uint32_t)(b_lrow * WSTR * 2 + b_lcol);
    const uint32_t wlo_base = smem_u32(Wlo) + (uint32_t)(b_lrow * WSTR * 2 + b_lcol);

    float acc[8][4];
    #pragma unroll
    for (int i = 0; i < 8; i++)
        #pragma unroll
        for (int j = 0; j < 4; j++) acc[i][j] = 0.0f;

    for (int kt = 0; kt < DMODEL / 64; kt++) {
        const int k0 = kt * 64;
        __syncthreads();
        #pragma unroll
        for (int i = 0; i < 8; i++) {
            int f = tid + i * 256;
            int r = f >> 4, c4 = (f & 15) * 4;
            float4 xv = *reinterpret_cast<const float4*>(
                &X[(size_t)(row0 + r) * DMODEL + k0 + c4]);
            *(uint32_t*)&Xhi[r * XSTR + c4]     = pack_hi_pair(xv.x, xv.y);
            *(uint32_t*)&Xhi[r * XSTR + c4 + 2] = pack_hi_pair(xv.z, xv.w);
            *(uint32_t*)&Xlo[r * XSTR + c4]     = pack_lo_pair(xv.x, xv.y);
            *(uint32_t*)&Xlo[r * XSTR + c4 + 2] = pack_lo_pair(xv.z, xv.w);
        }
        #pragma unroll
        for (int i = 0; i < 4; i++) {
            int f = tid + i * 256;
            int r = f >> 4, c4 = (f & 15) * 4;
            float4 wv = *reinterpret_cast<const float4*>(
                &W[(size_t)(k0 + r) * DK + c4]);
            Whi[(c4 + 0) * WSTR + r] = hi16(wv.x);
            Whi[(c4 + 1) * WSTR + r] = hi16(wv.y);
            Whi[(c4 + 2) * WSTR + r] = hi16(wv.z);
            Whi[(c4 + 3) * WSTR + r] = hi16(wv.w);
            Wlo[(c4 + 0) * WSTR + r] = lo16(wv.x);
            Wlo[(c4 + 1) * WSTR + r] = lo16(wv.y);
            Wlo[(c4 + 2) * WSTR + r] = lo16(wv.z);
            Wlo[(c4 + 3) * WSTR + r] = lo16(wv.w);
        }
        __syncthreads();

        #pragma unroll
        for (int kb = 0; kb < 4; kb++) {
            const uint32_t aoff = (uint32_t)(kb * 32);   // 16 halves
            uint32_t ah[4], al[4];
            ldsm_x4(ah, xhi_base + aoff);
            ldsm_x4(al, xlo_base + aoff);
            #pragma unroll
            for (int pr = 0; pr < 4; pr++) {             // n-block pairs
                const uint32_t boff = (uint32_t)(pr * 16 * WSTR * 2 + kb * 32);
                uint32_t bh[4], bl[4];
                ldsm_x4(bh, whi_base + boff);
                ldsm_x4(bl, wlo_base + boff);
                mma_bf16(acc[pr*2],   ah, bh[0], bh[1]);
                mma_bf16(acc[pr*2],   ah, bl[0], bl[1]);
                mma_bf16(acc[pr*2],   al, bh[0], bh[1]);
                mma_bf16(acc[pr*2+1], ah, bh[2], bh[3]);
                mma_bf16(acc[pr*2+1], ah, bl[2], bl[3]);
                mma_bf16(acc[pr*2+1], al, bh[2], bh[3]);
            }
        }
    }

    const int r0 = row0 + w * 16 + qr;
    #pragma unroll
    for (int nb = 0; nb < 8; nb++) {
        const int n = nb * 8 + qc * 2;
        float bx = bias[n], by = bias[n + 1];
        float ax = acc[nb][0] + bx, ay = acc[nb][1] + by;
        float cx = acc[nb][2] + bx, cy = acc[nb][3] + by;
        if (which == 1) {
            *(uint32_t*)&g_Khi[(size_t)r0 * DK + n]       = pack_hi_pair(ax, ay);
            *(uint32_t*)&g_Klo[(size_t)r0 * DK + n]       = pack_lo_pair(ax, ay);
            *(uint32_t*)&g_Khi[(size_t)(r0 + 8) * DK + n] = pack_hi_pair(cx, cy);
            *(uint32_t*)&g_Klo[(size_t)(r0 + 8) * DK + n] = pack_lo_pair(cx, cy);
        } else {
            float* dst = (which == 0) ? g_Q : g_V;
            const float s = (which == 0) ? 0.125f : 1.0f;
            float2 v0, v1;
            v0.x = ax * s; v0.y = ay * s;
            v1.x = cx * s; v1.y = cy * s;
            *reinterpret_cast<float2*>(&dst[(size_t)r0 * DK + n]) = v0;
            *reinterpret_cast<float2*>(&dst[(size_t)(r0 + 8) * DK + n]) = v1;
        }
    }
}

// ---------------------------------------------------------------------------
// V^T hi/lo transpose (identical to 137.6us build)
// ---------------------------------------------------------------------------
__global__ __launch_bounds__(256) void vt_convert_kernel()
{
    __shared__ float t[128][65];
    const int b = blockIdx.y, s0 = blockIdx.x * 128;
    const int tid = threadIdx.x;
    #pragma unroll
    for (int i = 0; i < 32; i++) {
        int idx = tid + i * 256;
        int r = idx >> 6, d = idx & 63;
        t[r][d] = g_V[((size_t)b * SEQ + s0 + r) * DK + d];
    }
    __syncthreads();
    #pragma unroll
    for (int i = 0; i < 16; i++) {
        int idx = tid + i * 256;
        int d = idx >> 6, sp = idx & 63;
        float a = t[sp * 2][d], c = t[sp * 2 + 1][d];
        size_t off = ((size_t)b * DK + d) * SEQ + s0 + sp * 2;
        *(uint32_t*)&g_VThi[off] = pack_hi_pair(a, c);
        *(uint32_t*)&g_VTlo[off] = pack_lo_pair(a, c);
    }
}

// ---------------------------------------------------------------------------
// mma split-K causal attention with ldmatrix B-fragments (137.6us build).
// 64 queries/CTA (128 thr, 4 warps), 128-key tiles. Grid (32, NCHUNK, 8).
// ---------------------------------------------------------------------------
__global__ __launch_bounds__(128, 3) void attn_mma_kernel()
{
    extern __shared__ unsigned short asm_[];
    unsigned short* Khi = asm_;                   // 128*KSTR
    unsigned short* Klo = Khi + 128 * KSTR;
    unsigned short* Vhi = Klo + 128 * KSTR;       // V^T: 64*VSTR
    unsigned short* Vlo = Vhi + 64 * VSTR;

    const int qtile = blockIdx.x, chunk = blockIdx.y, b = blockIdx.z;
    const int q0 = qtile * 64;
    const int kbeg = chunk * CHUNK;
    if (kbeg >= q0 + 64) return;
    const int kend = min(kbeg + CHUNK, q0 + 64);
    const int ntiles = (kend - kbeg + 127) >> 7;

    const int tid = threadIdx.x;
    const int w = tid >> 5, lane = tid & 31;
    const int qr = lane >> 2, qc = lane & 3;

    const int lrow = ((lane >> 4) & 1) * 8 + (lane & 7);
    const int lcol = ((lane >> 3) & 1) * 16;
    const uint32_t k_lsel = (uint32_t)(lrow * KSTR * 2 + lcol);
    const uint32_t v_lsel = (uint32_t)(lrow * VSTR * 2 + lcol);
    const uint32_t khi_base = smem_u32(Khi) + k_lsel;
    const uint32_t klo_base = smem_u32(Klo) + k_lsel;
    const uint32_t vhi_base = smem_u32(Vhi) + v_lsel;
    const uint32_t vlo_base = smem_u32(Vlo) + v_lsel;

    // Q fragments (persistent)
    uint32_t qh[4][4], ql[4][4];
    {
        const float* Qp = g_Q + ((size_t)b * SEQ + q0 + w * 16) * DK;
        #pragma unroll
        for (int kb = 0; kb < 4; kb++) {
            const int c0 = kb * 16 + qc * 2;
            float2 x00 = *reinterpret_cast<const float2*>(&Qp[(size_t)qr * DK + c0]);
            float2 x10 = *reinterpret_cast<const float2*>(&Qp[(size_t)(qr + 8) * DK + c0]);
            float2 x01 = *reinterpret_cast<const float2*>(&Qp[(size_t)qr * DK + c0 + 8]);
            float2 x11 = *reinterpret_cast<const float2*>(&Qp[(size_t)(qr + 8) * DK + c0 + 8]);
            qh[kb][0] = pack_hi_pair(x00.x, x00.y); ql[kb][0] = pack_lo_pair(x00.x, x00.y);
            qh[kb][1] = pack_hi_pair(x10.x, x10.y); ql[kb][1] = pack_lo_pair(x10.x, x10.y);
            qh[kb][2] = pack_hi_pair(x01.x, x01.y); ql[kb][2] = pack_lo_pair(x01.x, x01.y);
            qh[kb][3] = pack_hi_pair(x11.x, x11.y); ql[kb][3] = pack_lo_pair(x11.x, x11.y);
        }
    }

    float oacc[8][4];
    #pragma unroll
    for (int i = 0; i < 8; i++)
        #pragma unroll
        for (int j = 0; j < 4; j++) oacc[i][j] = 0.0f;
    float lsum0 = 0.0f, lsum1 = 0.0f;

    const int rowlo = q0 + w * 16 + qr;
    const int rowhi = rowlo + 8;

    for (int t = 0; t < ntiles; t++) {
        const int k0 = kbeg + t * 128;
        __syncthreads();
        #pragma unroll
        for (int i = 0; i < 8; i++) {
            int idx = tid + i * 128;
            int row = idx >> 3, u = idx & 7;
            const size_t gsrc = ((size_t)b * SEQ + k0 + row) * DK;
            *reinterpret_cast<uint4*>(&Khi[row * KSTR + u * 8]) =
                reinterpret_cast<const uint4*>(g_Khi + gsrc)[u];
            *reinterpret_cast<uint4*>(&Klo[row * KSTR + u * 8]) =
                reinterpret_cast<const uint4*>(g_Klo + gsrc)[u];
        }
        #pragma unroll
        for (int i = 0; i < 8; i++) {
            int idx = tid + i * 128;
            int d = idx >> 4, u = idx & 15;
            const size_t gsrc = ((size_t)b * DK + d) * SEQ + k0;
            *reinterpret_cast<uint4*>(&Vhi[d * VSTR + u * 8]) =
                reinterpret_cast<const uint4*>(g_VThi + gsrc)[u];
            *reinterpret_cast<uint4*>(&Vlo[d * VSTR + u * 8]) =
                reinterpret_cast<const uint4*>(g_VTlo + gsrc)[u];
        }
        __syncthreads();

        // ---- S = Q K^T ----
        float sc[16][4];
        #pragma unroll
        for (int i = 0; i < 16; i++)
            #pragma unroll
            for (int j = 0; j < 4; j++) sc[i][j] = 0.0f;

        #pragma unroll
        for (int kb = 0; kb < 4; kb++) {
            #pragma unroll
            for (int pr = 0; pr < 8; pr++) {
                const uint32_t off = (uint32_t)(pr * 16 * KSTR * 2 + kb * 32);
                uint32_t bh[4], bl[4];
                ldsm_x4(bh, khi_base + off);
                ldsm_x4(bl, klo_base + off);
                mma_bf16(sc[pr*2],   qh[kb], bh[0], bh[1]);
                mma_bf16(sc[pr*2],   qh[kb], bl[0], bl[1]);
                mma_bf16(sc[pr*2],   ql[kb], bh[0], bh[1]);
                mma_bf16(sc[pr*2+1], qh[kb], bh[2], bh[3]);
                mma_bf16(sc[pr*2+1], qh[kb], bl[2], bl[3]);
                mma_bf16(sc[pr*2+1], ql[kb], bh[2], bh[3]);
            }
        }

        // ---- p = mask ? exp(s) : 0 ----
        #pragma unroll
        for (int nb = 0; nb < 16; nb++) {
            const int col0 = k0 + nb * 8 + qc * 2;
            float p0 = (col0     <= rowlo) ? __expf(sc[nb][0]) : 0.0f;
            float p1 = (col0 + 1 <= rowlo) ? __expf(sc[nb][1]) : 0.0f;
            float p2 = (col0     <= rowhi) ? __expf(sc[nb][2]) : 0.0f;
            float p3 = (col0 + 1 <= rowhi) ? __expf(sc[nb][3]) : 0.0f;
            lsum0 += p0 + p1;
            lsum1 += p2 + p3;
            sc[nb][0] = p0; sc[nb][1] = p1; sc[nb][2] = p2; sc[nb][3] = p3;
        }

        // ---- O += P V ----
        #pragma unroll
        for (int kb2 = 0; kb2 < 8; kb2++) {
            uint32_t pah[4], pal[4];
            pah[0] = pack_hi_pair(sc[2*kb2][0],   sc[2*kb2][1]);
            pah[1] = pack_hi_pair(sc[2*kb2][2],   sc[2*kb2][3]);
            pah[2] = pack_hi_pair(sc[2*kb2+1][0], sc[2*kb2+1][1]);
            pah[3] = pack_hi_pair(sc[2*kb2+1][2], sc[2*kb2+1][3]);
            pal[0] = pack_lo_pair(sc[2*kb2][0],   sc[2*kb2][1]);
            pal[1] = pack_lo_pair(sc[2*kb2][2],   sc[2*kb2][3]);
            pal[2] = pack_lo_pair(sc[2*kb2+1][0], sc[2*kb2+1][1]);
            pal[3] = pack_lo_pair(sc[2*kb2+1][2], sc[2*kb2+1][3]);
            #pragma unroll
            for (int pr = 0; pr < 4; pr++) {
                const uint32_t off = (uint32_t)(pr * 16 * VSTR * 2 + kb2 * 32);
                uint32_t bh[4], bl[4];
                ldsm_x4(bh, vhi_base + off);
                ldsm_x4(bl, vlo_base + off);
                mma_bf16(oacc[pr*2],   pah, bh[0], bh[1]);
                mma_bf16(oacc[pr*2],   pah, bl[0], bl[1]);
                mma_bf16(oacc[pr*2],   pal, bh[0], bh[1]);
                mma_bf16(oacc[pr*2+1], pah, bh[2], bh[3]);
                mma_bf16(oacc[pr*2+1], pah, bl[2], bl[3]);
                mma_bf16(oacc[pr*2+1], pal, bh[2], bh[3]);
            }
        }
    }

    lsum0 += __shfl_xor_sync(0xFFFFFFFFu, lsum0, 1);
    lsum0 += __shfl_xor_sync(0xFFFFFFFFu, lsum0, 2);
    lsum1 += __shfl_xor_sync(0xFFFFFFFFu, lsum1, 1);
    lsum1 += __shfl_xor_sync(0xFFFFFFFFu, lsum1, 2);

    const size_t lbase = (size_t)(chunk * BATCH + b) * SEQ + q0 + w * 16;
    if (qc == 0) {
        g_pl[lbase + qr]     = lsum0;
        g_pl[lbase + qr + 8] = lsum1;
    }

    const size_t obase = ((size_t)(chunk * BATCH + b) * SEQ + q0 + w * 16 + qr) * DK;
    #pragma unroll
    for (int db = 0; db < 8; db++) {
        const int n = db * 8 + qc * 2;
        float2 v0, v1;
        v0.x = oacc[db][0]; v0.y = oacc[db][1];
        v1.x = oacc[db][2]; v1.y = oacc[db][3];
        *reinterpret_cast<float2*>(&g_pacc[obase + n]) = v0;
        *reinterpret_cast<float2*>(&g_pacc[obase + 8 * DK + n]) = v1;
    }
}

// ---------------------------------------------------------------------------
// Combine
// ---------------------------------------------------------------------------
__global__ __launch_bounds__(256) void combine_kernel(float* __restrict__ O)
{
    const int idx = blockIdx.x * 256 + threadIdx.x;
    const int qg = idx >> 6;
    const int d  = idx & 63;
    float sa = 0.0f, sl = 0.0f;
    #pragma unroll
    for (int c = 0; c < NCHUNK; c++) {
        sa += g_pacc[((size_t)c * BATCH * SEQ + qg) * DK + d];
        sl += g_pl[(size_t)c * BATCH * SEQ + qg];
    }
    O[idx] = sa / sl;
}

extern "C" void kernel_launch(void* const* d_in, const int* in_sizes, int n_in,
                              void* d_out, int out_size)
{
    const float* qs = (const float*)d_in[0];
    const float* ks = (const float*)d_in[1];
    const float* vs = (const float*)d_in[2];
    // d_in[3] = mask — causal structure handled analytically
    const float* Wq = (const float*)d_in[4];
    const float* bq = (const float*)d_in[5];
    const float* Wk = (const float*)d_in[6];
    const float* bk = (const float*)d_in[7];
    const float* Wv = (const float*)d_in[8];
    const float* bv = (const float*)d_in[9];
    float* out = (float*)d_out;
    (void)in_sizes; (void)n_in; (void)out_size;

    const int proj_smem = (2 * 128 * XSTR + 2 * 64 * WSTR) * 2;   // 55296 B
    const int attn_smem = (2 * 128 * KSTR + 2 * 64 * VSTR) * 2;   // 71680 B
    cudaFuncSetAttribute(proj_mma_kernel, cudaFuncAttributeMaxDynamicSharedMemorySize, proj_smem);
    cudaFuncSetAttribute(attn_mma_kernel, cudaFuncAttributeMaxDynamicSharedMemorySize, attn_smem);

    dim3 pgrid(128, 3);
    proj_mma_kernel<<<pgrid, 256, proj_smem>>>(qs, ks, vs, Wq, bq, Wk, bk, Wv, bv);

    dim3 cgrid(SEQ / 128, BATCH);
    vt_convert_kernel<<<cgrid, 256>>>();

    dim3 agrid(SEQ / 64, NCHUNK, BATCH);
    attn_mma_kernel<<<agrid, 128, attn_smem>>>();

    combine_kernel<<<(BATCH * SEQ * DK) / 256, 256>>>(out);
}

// round 10
// speedup vs baseline: 1.2146x; 1.0153x over previous
#include <cuda_runtime.h>
#include <cuda_bf16.h>
#include <math.h>
#include <stdint.h>

#define DMODEL 512
#define DK     64
#define BATCH  8
#define SEQ    2048
#define NCHUNK 4
#define CHUNK  (SEQ / NCHUNK)   // 512 keys per split-K chunk

// Scratch (device globals — no allocation allowed)
__device__ float g_Q[BATCH * SEQ * DK];                  // pre-scaled by 1/8
__device__ float g_V[BATCH * SEQ * DK];
__device__ unsigned short g_Khi[BATCH * SEQ * DK];       // bf16 trunc of K
__device__ unsigned short g_Klo[BATCH * SEQ * DK];       // bf16 residual of K
__device__ unsigned short g_VThi[BATCH * DK * SEQ];      // V^T bf16 hi
__device__ unsigned short g_VTlo[BATCH * DK * SEQ];      // V^T bf16 lo
__device__ float g_pacc[(size_t)NCHUNK * BATCH * SEQ * DK];
__device__ float g_pl[(size_t)NCHUNK * BATCH * SEQ];

// ===================== helpers =====================
__device__ __forceinline__ uint32_t pack_hi_pair(float a, float b) {
    return __byte_perm(__float_as_uint(a), __float_as_uint(b), 0x7632);
}
__device__ __forceinline__ uint32_t pack_lo_pair(float a, float b) {
    float la = a - __uint_as_float(__float_as_uint(a) & 0xFFFF0000u);
    float lb = b - __uint_as_float(__float_as_uint(b) & 0xFFFF0000u);
    uint32_t r;
    asm("cvt.rn.bf16x2.f32 %0, %1, %2;" : "=r"(r) : "f"(lb), "f"(la));
    return r;
}
__device__ __forceinline__ unsigned short hi16(float v) {
    return (unsigned short)(__float_as_uint(v) >> 16);
}
__device__ __forceinline__ unsigned short lo16(float v) {
    float r = v - __uint_as_float(__float_as_uint(v) & 0xFFFF0000u);
    unsigned short s;
    asm("cvt.rn.bf16.f32 %0, %1;" : "=h"(s) : "f"(r));
    return s;
}
__device__ __forceinline__ void mma_bf16(float* c, const uint32_t* a,
                                         uint32_t b0, uint32_t b1) {
    asm volatile(
        "mma.sync.aligned.m16n8k16.row.col.f32.bf16.bf16.f32 "
        "{%0,%1,%2,%3}, {%4,%5,%6,%7}, {%8,%9}, {%0,%1,%2,%3};"
        : "+f"(c[0]), "+f"(c[1]), "+f"(c[2]), "+f"(c[3])
        : "r"(a[0]), "r"(a[1]), "r"(a[2]), "r"(a[3]), "r"(b0), "r"(b1));
}
__device__ __forceinline__ void ldsm_x4(uint32_t* d, uint32_t saddr) {
    asm volatile("ldmatrix.sync.aligned.m8n8.x4.shared.b16 {%0,%1,%2,%3}, [%4];"
                 : "=r"(d[0]), "=r"(d[1]), "=r"(d[2]), "=r"(d[3]) : "r"(saddr));
}
__device__ __forceinline__ uint32_t smem_u32(const void* p) {
    return (uint32_t)__cvta_generic_to_shared(p);
}
__device__ __forceinline__ void cp_async16(uint32_t saddr, const void* gaddr) {
    asm volatile("cp.async.cg.shared.global [%0], [%1], 16;"
                 :: "r"(saddr), "l"(gaddr));
}
#define CP_COMMIT() asm volatile("cp.async.commit_group;" ::: "memory")
#define CP_WAIT0()  asm volatile("cp.async.wait_group 0;" ::: "memory")

// smem strides in bf16 halves: 16B-aligned rows AND conflict-free frag loads
#define KSTR 72    // K tile rows (128 x 64)
#define VSTR 136   // V^T tile rows (64 x 128)
#define XSTR 72
#define WSTR 72

// ---------------------------------------------------------------------------
// Projection via mma; cp.async staging pipeline hides DRAM latency behind mma.
// which: 0=Q (scaled 1/8, float out), 1=K (bf16 hi/lo out), 2=V (float out).
// ---------------------------------------------------------------------------
__global__ __launch_bounds__(256, 2) void proj_mma_kernel(
    const float* __restrict__ Xq, const float* __restrict__ Xk, const float* __restrict__ Xv,
    const float* __restrict__ Wq, const float* __restrict__ bq,
    const float* __restrict__ Wk, const float* __restrict__ bk,
    const float* __restrict__ Wv, const float* __restrict__ bv)
{
    extern __shared__ unsigned short psm[];
    unsigned short* Xhi = psm;                              // 128*XSTR halves
    unsigned short* Xlo = Xhi + 128 * XSTR;
    unsigned short* Whi = Xlo + 128 * XSTR;                 // 64*WSTR
    unsigned short* Wlo = Whi + 64 * WSTR;
    float* Xs = (float*)(Wlo + 64 * WSTR);                  // staging 128x64 f32
    float* Ws = Xs + 128 * 64;                              // staging 64x64 f32

    const int which = blockIdx.y;
    const float* __restrict__ X = (which == 0) ? Xq : (which == 1) ? Xk : Xv;
    const float* __restrict__ W = (which == 0) ? Wq : (which == 1) ? Wk : Wv;
    const float* __restrict__ bias = (which == 0) ? bq : (which == 1) ? bk : bv;

    const int row0 = blockIdx.x * 128;
    const int tid = threadIdx.x;
    const int w = tid >> 5, lane = tid & 31;
    const int qr = lane >> 2, qc = lane & 3;

    // ldmatrix lane->address maps (bytes)
    const int a_lrow = ((lane >> 3) & 1) * 8 + (lane & 7);
    const int a_lcol = ((lane >> 4) & 1) * 16;
    const int b_lrow = ((lane >> 4) & 1) * 8 + (lane & 7);
    const int b_lcol = ((lane >> 3) & 1) * 16;

    const uint32_t xhi_base = smem_u32(Xhi) + (uint32_t)((w * 16 + a_lrow) * XSTR * 2 + a_lcol);
    const uint32_t xlo_base = smem_u32(Xlo) + (uint32_t)((w * 16 + a_lrow) * XSTR * 2 + a_lcol);
    const uint32_t whi_base = smem_u32(Whi) + (uint32_t)(b_lrow * WSTR * 2 + b_lcol);
    const uint32_t wlo_base = smem_u32(Wlo) + (uint32_t)(b_lrow * WSTR * 2 + b_lcol);

    // copy coords: 16B chunks
    const int cr = tid >> 4, cc4 = (tid & 15) * 4;
    const uint32_t xs_s = smem_u32(Xs);
    const uint32_t ws_s = smem_u32(Ws);

    float acc[8][4];
    #pragma unroll
    for (int i = 0; i < 8; i++)
        #pragma unroll
        for (int j = 0; j < 4; j++) acc[i][j] = 0.0f;

    // prologue: stage tile 0
    #pragma unroll
    for (int i = 0; i < 8; i++) {
        int r = cr + i * 16;
        cp_async16(xs_s + (uint32_t)((r * 64 + cc4) * 4),
                   &X[(size_t)(row0 + r) * DMODEL + cc4]);
    }
    #pragma unroll
    for (int i = 0; i < 4; i++) {
        int r = cr + i * 16;
        cp_async16(ws_s + (uint32_t)((r * 64 + cc4) * 4),
                   &W[(size_t)r * DK + cc4]);
    }
    CP_COMMIT();

    for (int kt = 0; kt < DMODEL / 64; kt++) {
        CP_WAIT0();
        __syncthreads();           // staging ready; prior mma done (operand free)

        // convert staging -> hi/lo operand smem (smem->smem, low latency)
        #pragma unroll
        for (int i = 0; i < 8; i++) {
            int r = cr + i * 16;
            float4 xv = *reinterpret_cast<const float4*>(&Xs[r * 64 + cc4]);
            *(uint32_t*)&Xhi[r * XSTR + cc4]     = pack_hi_pair(xv.x, xv.y);
            *(uint32_t*)&Xhi[r * XSTR + cc4 + 2] = pack_hi_pair(xv.z, xv.w);
            *(uint32_t*)&Xlo[r * XSTR + cc4]     = pack_lo_pair(xv.x, xv.y);
            *(uint32_t*)&Xlo[r * XSTR + cc4 + 2] = pack_lo_pair(xv.z, xv.w);
        }
        #pragma unroll
        for (int i = 0; i < 4; i++) {
            int r = cr + i * 16;
            float4 wv = *reinterpret_cast<const float4*>(&Ws[r * 64 + cc4]);
            Whi[(cc4 + 0) * WSTR + r] = hi16(wv.x);
            Whi[(cc4 + 1) * WSTR + r] = hi16(wv.y);
            Whi[(cc4 + 2) * WSTR + r] = hi16(wv.z);
            Whi[(cc4 + 3) * WSTR + r] = hi16(wv.w);
            Wlo[(cc4 + 0) * WSTR + r] = lo16(wv.x);
            Wlo[(cc4 + 1) * WSTR + r] = lo16(wv.y);
            Wlo[(cc4 + 2) * WSTR + r] = lo16(wv.z);
            Wlo[(cc4 + 3) * WSTR + r] = lo16(wv.w);
        }
        __syncthreads();           // operands ready; staging free for next copy

        // stage tile kt+1 while mma runs
        if (kt + 1 < DMODEL / 64) {
            const int k0n = (kt + 1) * 64;
            #pragma unroll
            for (int i = 0; i < 8; i++) {
                int r = cr + i * 16;
                cp_async16(xs_s + (uint32_t)((r * 64 + cc4) * 4),
                           &X[(size_t)(row0 + r) * DMODEL + k0n + cc4]);
            }
            #pragma unroll
            for (int i = 0; i < 4; i++) {
                int r = cr + i * 16;
                cp_async16(ws_s + (uint32_t)((r * 64 + cc4) * 4),
                           &W[(size_t)(k0n + r) * DK + cc4]);
            }
            CP_COMMIT();
        }

        #pragma unroll
        for (int kb = 0; kb < 4; kb++) {
            const uint32_t aoff = (uint32_t)(kb * 32);
            uint32_t ah[4], al[4];
            ldsm_x4(ah, xhi_base + aoff);
            ldsm_x4(al, xlo_base + aoff);
            #pragma unroll
            for (int pr = 0; pr < 4; pr++) {
                const uint32_t boff = (uint32_t)(pr * 16 * WSTR * 2 + kb * 32);
                uint32_t bh[4], bl[4];
                ldsm_x4(bh, whi_base + boff);
                ldsm_x4(bl, wlo_base + boff);
                mma_bf16(acc[pr*2],   ah, bh[0], bh[1]);
                mma_bf16(acc[pr*2],   ah, bl[0], bl[1]);
                mma_bf16(acc[pr*2],   al, bh[0], bh[1]);
                mma_bf16(acc[pr*2+1], ah, bh[2], bh[3]);
                mma_bf16(acc[pr*2+1], ah, bl[2], bl[3]);
                mma_bf16(acc[pr*2+1], al, bh[2], bh[3]);
            }
        }
    }

    const int r0 = row0 + w * 16 + qr;
    #pragma unroll
    for (int nb = 0; nb < 8; nb++) {
        const int n = nb * 8 + qc * 2;
        float bx = bias[n], by = bias[n + 1];
        float ax = acc[nb][0] + bx, ay = acc[nb][1] + by;
        float cx = acc[nb][2] + bx, cy = acc[nb][3] + by;
        if (which == 1) {
            *(uint32_t*)&g_Khi[(size_t)r0 * DK + n]       = pack_hi_pair(ax, ay);
            *(uint32_t*)&g_Klo[(size_t)r0 * DK + n]       = pack_lo_pair(ax, ay);
            *(uint32_t*)&g_Khi[(size_t)(r0 + 8) * DK + n] = pack_hi_pair(cx, cy);
            *(uint32_t*)&g_Klo[(size_t)(r0 + 8) * DK + n] = pack_lo_pair(cx, cy);
        } else {
            float* dst = (which == 0) ? g_Q : g_V;
            const float s = (which == 0) ? 0.125f : 1.0f;
            float2 v0, v1;
            v0.x = ax * s; v0.y = ay * s;
            v1.x = cx * s; v1.y = cy * s;
            *reinterpret_cast<float2*>(&dst[(size_t)r0 * DK + n]) = v0;
            *reinterpret_cast<float2*>(&dst[(size_t)(r0 + 8) * DK + n]) = v1;
        }
    }
}

// ---------------------------------------------------------------------------
// V^T hi/lo transpose (identical to 135.6us build)
// ---------------------------------------------------------------------------
__global__ __launch_bounds__(256) void vt_convert_kernel()
{
    __shared__ float t[128][65];
    const int b = blockIdx.y, s0 = blockIdx.x * 128;
    const int tid = threadIdx.x;
    #pragma unroll
    for (int i = 0; i < 32; i++) {
        int idx = tid + i * 256;
        int r = idx >> 6, d = idx & 63;
        t[r][d] = g_V[((size_t)b * SEQ + s0 + r) * DK + d];
    }
    __syncthreads();
    #pragma unroll
    for (int i = 0; i < 16; i++) {
        int idx = tid + i * 256;
        int d = idx >> 6, sp = idx & 63;
        float a = t[sp * 2][d], c = t[sp * 2 + 1][d];
        size_t off = ((size_t)b * DK + d) * SEQ + s0 + sp * 2;
        *(uint32_t*)&g_VThi[off] = pack_hi_pair(a, c);
        *(uint32_t*)&g_VTlo[off] = pack_lo_pair(a, c);
    }
}

// ---------------------------------------------------------------------------
// mma split-K causal attention with ldmatrix B-fragments (135.6us build).
// ---------------------------------------------------------------------------
__global__ __launch_bounds__(128, 3) void attn_mma_kernel()
{
    extern __shared__ unsigned short asm_[];
    unsigned short* Khi = asm_;
    unsigned short* Klo = Khi + 128 * KSTR;
    unsigned short* Vhi = Klo + 128 * KSTR;
    unsigned short* Vlo = Vhi + 64 * VSTR;

    const int qtile = blockIdx.x, chunk = blockIdx.y, b = blockIdx.z;
    const int q0 = qtile * 64;
    const int kbeg = chunk * CHUNK;
    if (kbeg >= q0 + 64) return;
    const int kend = min(kbeg + CHUNK, q0 + 64);
    const int ntiles = (kend - kbeg + 127) >> 7;

    const int tid = threadIdx.x;
    const int w = tid >> 5, lane = tid & 31;
    const int qr = lane >> 2, qc = lane & 3;

    const int lrow = ((lane >> 4) & 1) * 8 + (lane & 7);
    const int lcol = ((lane >> 3) & 1) * 16;
    const uint32_t k_lsel = (uint32_t)(lrow * KSTR * 2 + lcol);
    const uint32_t v_lsel = (uint32_t)(lrow * VSTR * 2 + lcol);
    const uint32_t khi_base = smem_u32(Khi) + k_lsel;
    const uint32_t klo_base = smem_u32(Klo) + k_lsel;
    const uint32_t vhi_base = smem_u32(Vhi) + v_lsel;
    const uint32_t vlo_base = smem_u32(Vlo) + v_lsel;

    uint32_t qh[4][4], ql[4][4];
    {
        const float* Qp = g_Q + ((size_t)b * SEQ + q0 + w * 16) * DK;
        #pragma unroll
        for (int kb = 0; kb < 4; kb++) {
            const int c0 = kb * 16 + qc * 2;
            float2 x00 = *reinterpret_cast<const float2*>(&Qp[(size_t)qr * DK + c0]);
            float2 x10 = *reinterpret_cast<const float2*>(&Qp[(size_t)(qr + 8) * DK + c0]);
            float2 x01 = *reinterpret_cast<const float2*>(&Qp[(size_t)qr * DK + c0 + 8]);
            float2 x11 = *reinterpret_cast<const float2*>(&Qp[(size_t)(qr + 8) * DK + c0 + 8]);
            qh[kb][0] = pack_hi_pair(x00.x, x00.y); ql[kb][0] = pack_lo_pair(x00.x, x00.y);
            qh[kb][1] = pack_hi_pair(x10.x, x10.y); ql[kb][1] = pack_lo_pair(x10.x, x10.y);
            qh[kb][2] = pack_hi_pair(x01.x, x01.y); ql[kb][2] = pack_lo_pair(x01.x, x01.y);
            qh[kb][3] = pack_hi_pair(x11.x, x11.y); ql[kb][3] = pack_lo_pair(x11.x, x11.y);
        }
    }

    float oacc[8][4];
    #pragma unroll
    for (int i = 0; i < 8; i++)
        #pragma unroll
        for (int j = 0; j < 4; j++) oacc[i][j] = 0.0f;
    float lsum0 = 0.0f, lsum1 = 0.0f;

    const int rowlo = q0 + w * 16 + qr;
    const int rowhi = rowlo + 8;

    for (int t = 0; t < ntiles; t++) {
        const int k0 = kbeg + t * 128;
        __syncthreads();
        #pragma unroll
        for (int i = 0; i < 8; i++) {
            int idx = tid + i * 128;
            int row = idx >> 3, u = idx & 7;
            const size_t gsrc = ((size_t)b * SEQ + k0 + row) * DK;
            *reinterpret_cast<uint4*>(&Khi[row * KSTR + u * 8]) =
                reinterpret_cast<const uint4*>(g_Khi + gsrc)[u];
            *reinterpret_cast<uint4*>(&Klo[row * KSTR + u * 8]) =
                reinterpret_cast<const uint4*>(g_Klo + gsrc)[u];
        }
        #pragma unroll
        for (int i = 0; i < 8; i++) {
            int idx = tid + i * 128;
            int d = idx >> 4, u = idx & 15;
            const size_t gsrc = ((size_t)b * DK + d) * SEQ + k0;
            *reinterpret_cast<uint4*>(&Vhi[d * VSTR + u * 8]) =
                reinterpret_cast<const uint4*>(g_VThi + gsrc)[u];
            *reinterpret_cast<uint4*>(&Vlo[d * VSTR + u * 8]) =
                reinterpret_cast<const uint4*>(g_VTlo + gsrc)[u];
        }
        __syncthreads();

        float sc[16][4];
        #pragma unroll
        for (int i = 0; i < 16; i++)
            #pragma unroll
            for (int j = 0; j < 4; j++) sc[i][j] = 0.0f;

        #pragma unroll
        for (int kb = 0; kb < 4; kb++) {
            #pragma unroll
            for (int pr = 0; pr < 8; pr++) {
                const uint32_t off = (uint32_t)(pr * 16 * KSTR * 2 + kb * 32);
                uint32_t bh[4], bl[4];
                ldsm_x4(bh, khi_base + off);
                ldsm_x4(bl, klo_base + off);
                mma_bf16(sc[pr*2],   qh[kb], bh[0], bh[1]);
                mma_bf16(sc[pr*2],   qh[kb], bl[0], bl[1]);
                mma_bf16(sc[pr*2],   ql[kb], bh[0], bh[1]);
                mma_bf16(sc[pr*2+1], qh[kb], bh[2], bh[3]);
                mma_bf16(sc[pr*2+1], qh[kb], bl[2], bl[3]);
                mma_bf16(sc[pr*2+1], ql[kb], bh[2], bh[3]);
            }
        }

        #pragma unroll
        for (int nb = 0; nb < 16; nb++) {
            const int col0 = k0 + nb * 8 + qc * 2;
            float p0 = (col0     <= rowlo) ? __expf(sc[nb][0]) : 0.0f;
            float p1 = (col0 + 1 <= rowlo) ? __expf(sc[nb][1]) : 0.0f;
            float p2 = (col0     <= rowhi) ? __expf(sc[nb][2]) : 0.0f;
            float p3 = (col0 + 1 <= rowhi) ? __expf(sc[nb][3]) : 0.0f;
            lsum0 += p0 + p1;
            lsum1 += p2 + p3;
            sc[nb][0] = p0; sc[nb][1] = p1; sc[nb][2] = p2; sc[nb][3] = p3;
        }

        #pragma unroll
        for (int kb2 = 0; kb2 < 8; kb2++) {
            uint32_t pah[4], pal[4];
            pah[0] = pack_hi_pair(sc[2*kb2][0],   sc[2*kb2][1]);
            pah[1] = pack_hi_pair(sc[2*kb2][2],   sc[2*kb2][3]);
            pah[2] = pack_hi_pair(sc[2*kb2+1][0], sc[2*kb2+1][1]);
            pah[3] = pack_hi_pair(sc[2*kb2+1][2], sc[2*kb2+1][3]);
            pal[0] = pack_lo_pair(sc[2*kb2][0],   sc[2*kb2][1]);
            pal[1] = pack_lo_pair(sc[2*kb2][2],   sc[2*kb2][3]);
            pal[2] = pack_lo_pair(sc[2*kb2+1][0], sc[2*kb2+1][1]);
            pal[3] = pack_lo_pair(sc[2*kb2+1][2], sc[2*kb2+1][3]);
            #pragma unroll
            for (int pr = 0; pr < 4; pr++) {
                const uint32_t off = (uint32_t)(pr * 16 * VSTR * 2 + kb2 * 32);
                uint32_t bh[4], bl[4];
                ldsm_x4(bh, vhi_base + off);
                ldsm_x4(bl, vlo_base + off);
                mma_bf16(oacc[pr*2],   pah, bh[0], bh[1]);
                mma_bf16(oacc[pr*2],   pah, bl[0], bl[1]);
                mma_bf16(oacc[pr*2],   pal, bh[0], bh[1]);
                mma_bf16(oacc[pr*2+1], pah, bh[2], bh[3]);
                mma_bf16(oacc[pr*2+1], pah, bl[2], bl[3]);
                mma_bf16(oacc[pr*2+1], pal, bh[2], bh[3]);
            }
        }
    }

    lsum0 += __shfl_xor_sync(0xFFFFFFFFu, lsum0, 1);
    lsum0 += __shfl_xor_sync(0xFFFFFFFFu, lsum0, 2);
    lsum1 += __shfl_xor_sync(0xFFFFFFFFu, lsum1, 1);
    lsum1 += __shfl_xor_sync(0xFFFFFFFFu, lsum1, 2);

    const size_t lbase = (size_t)(chunk * BATCH + b) * SEQ + q0 + w * 16;
    if (qc == 0) {
        g_pl[lbase + qr]     = lsum0;
        g_pl[lbase + qr + 8] = lsum1;
    }

    const size_t obase = ((size_t)(chunk * BATCH + b) * SEQ + q0 + w * 16 + qr) * DK;
    #pragma unroll
    for (int db = 0; db < 8; db++) {
        const int n = db * 8 + qc * 2;
        float2 v0, v1;
        v0.x = oacc[db][0]; v0.y = oacc[db][1];
        v1.x = oacc[db][2]; v1.y = oacc[db][3];
        *reinterpret_cast<float2*>(&g_pacc[obase + n]) = v0;
        *reinterpret_cast<float2*>(&g_pacc[obase + 8 * DK + n]) = v1;
    }
}

// ---------------------------------------------------------------------------
// Combine
// ---------------------------------------------------------------------------
__global__ __launch_bounds__(256) void combine_kernel(float* __restrict__ O)
{
    const int idx = blockIdx.x * 256 + threadIdx.x;
    const int qg = idx >> 6;
    const int d  = idx & 63;
    float sa = 0.0f, sl = 0.0f;
    #pragma unroll
    for (int c = 0; c < NCHUNK; c++) {
        sa += g_pacc[((size_t)c * BATCH * SEQ + qg) * DK + d];
        sl += g_pl[(size_t)c * BATCH * SEQ + qg];
    }
    O[idx] = sa / sl;
}

extern "C" void kernel_launch(void* const* d_in, const int* in_sizes, int n_in,
                              void* d_out, int out_size)
{
    const float* qs = (const float*)d_in[0];
    const float* ks = (const float*)d_in[1];
    const float* vs = (const float*)d_in[2];
    // d_in[3] = mask — causal structure handled analytically
    const float* Wq = (const float*)d_in[4];
    const float* bq = (const float*)d_in[5];
    const float* Wk = (const float*)d_in[6];
    const float* bk = (const float*)d_in[7];
    const float* Wv = (const float*)d_in[8];
    const float* bv = (const float*)d_in[9];
    float* out = (float*)d_out;
    (void)in_sizes; (void)n_in; (void)out_size;

    const int proj_smem = (2 * 128 * XSTR + 2 * 64 * WSTR) * 2     // operands 55296
                        + (128 * 64 + 64 * 64) * 4;                // staging 49152
    const int attn_smem = (2 * 128 * KSTR + 2 * 64 * VSTR) * 2;    // 71680 B
    cudaFuncSetAttribute(proj_mma_kernel, cudaFuncAttributeMaxDynamicSharedMemorySize, proj_smem);
    cudaFuncSetAttribute(attn_mma_kernel, cudaFuncAttributeMaxDynamicSharedMemorySize, attn_smem);

    dim3 pgrid(128, 3);
    proj_mma_kernel<<<pgrid, 256, proj_smem>>>(qs, ks, vs, Wq, bq, Wk, bk, Wv, bv);

    dim3 cgrid(SEQ / 128, BATCH);
    vt_convert_kernel<<<cgrid, 256>>>();

    dim3 agrid(SEQ / 64, NCHUNK, BATCH);
    attn_mma_kernel<<<agrid, 128, attn_smem>>>();

    combine_kernel<<<(BATCH * SEQ * DK) / 256, 256>>>(out);
}

// round 11
// speedup vs baseline: 1.2552x; 1.0334x over previous
#include <cuda_runtime.h>
#include <cuda_bf16.h>
#include <math.h>
#include <stdint.h>

#define DMODEL 512
#define DK     64
#define BATCH  8
#define SEQ    2048
#define NCHUNK 4
#define CHUNK  (SEQ / NCHUNK)   // 512 keys per split-K chunk

// Scratch (device globals — no allocation allowed)
__device__ float g_Q[BATCH * SEQ * DK];                  // pre-scaled by 1/8
__device__ unsigned short g_Khi[BATCH * SEQ * DK];       // bf16 trunc of K
__device__ unsigned short g_Klo[BATCH * SEQ * DK];       // bf16 residual of K
__device__ unsigned short g_VThi[BATCH * DK * SEQ];      // V^T bf16 hi
__device__ unsigned short g_VTlo[BATCH * DK * SEQ];      // V^T bf16 lo
__device__ float g_pacc[(size_t)NCHUNK * BATCH * SEQ * DK];
__device__ float g_pl[(size_t)NCHUNK * BATCH * SEQ];

// ===================== helpers =====================
__device__ __forceinline__ uint32_t pack_hi_pair(float a, float b) {
    return __byte_perm(__float_as_uint(a), __float_as_uint(b), 0x7632);
}
__device__ __forceinline__ uint32_t pack_lo_pair(float a, float b) {
    float la = a - __uint_as_float(__float_as_uint(a) & 0xFFFF0000u);
    float lb = b - __uint_as_float(__float_as_uint(b) & 0xFFFF0000u);
    uint32_t r;
    asm("cvt.rn.bf16x2.f32 %0, %1, %2;" : "=r"(r) : "f"(lb), "f"(la));
    return r;
}
__device__ __forceinline__ unsigned short hi16(float v) {
    return (unsigned short)(__float_as_uint(v) >> 16);
}
__device__ __forceinline__ unsigned short lo16(float v) {
    float r = v - __uint_as_float(__float_as_uint(v) & 0xFFFF0000u);
    unsigned short s;
    asm("cvt.rn.bf16.f32 %0, %1;" : "=h"(s) : "f"(r));
    return s;
}
__device__ __forceinline__ void mma_bf16(float* c, const uint32_t* a,
                                         uint32_t b0, uint32_t b1) {
    asm volatile(
        "mma.sync.aligned.m16n8k16.row.col.f32.bf16.bf16.f32 "
        "{%0,%1,%2,%3}, {%4,%5,%6,%7}, {%8,%9}, {%0,%1,%2,%3};"
        : "+f"(c[0]), "+f"(c[1]), "+f"(c[2]), "+f"(c[3])
        : "r"(a[0]), "r"(a[1]), "r"(a[2]), "r"(a[3]), "r"(b0), "r"(b1));
}
__device__ __forceinline__ void ldsm_x4(uint32_t* d, uint32_t saddr) {
    asm volatile("ldmatrix.sync.aligned.m8n8.x4.shared.b16 {%0,%1,%2,%3}, [%4];"
                 : "=r"(d[0]), "=r"(d[1]), "=r"(d[2]), "=r"(d[3]) : "r"(saddr));
}
__device__ __forceinline__ uint32_t smem_u32(const void* p) {
    return (uint32_t)__cvta_generic_to_shared(p);
}
__device__ __forceinline__ void cp_async16(uint32_t saddr, const void* gaddr) {
    asm volatile("cp.async.cg.shared.global [%0], [%1], 16;"
                 :: "r"(saddr), "l"(gaddr));
}
#define CP_COMMIT() asm volatile("cp.async.commit_group;" ::: "memory")
#define CP_WAIT0()  asm volatile("cp.async.wait_group 0;" ::: "memory")

// smem strides in bf16 halves: 16B-aligned rows AND conflict-free frag loads
#define KSTR 72    // K tile rows (128 x 64)
#define VSTR 136   // V^T tile rows (64 x 128)
#define XSTR 72
#define WSTR 72
#define TSTR 67    // fp32 transpose scratch stride (odd -> low-conflict reads)

// ---------------------------------------------------------------------------
// Projection via mma; cp.async staging pipeline; V written directly as
// transposed bf16 hi/lo (vt_convert fused into epilogue).
// which: 0=Q (scaled 1/8, float out), 1=K (bf16 hi/lo out), 2=V (VT hi/lo out).
// ---------------------------------------------------------------------------
__global__ __launch_bounds__(256, 2) void proj_mma_kernel(
    const float* __restrict__ Xq, const float* __restrict__ Xk, const float* __restrict__ Xv,
    const float* __restrict__ Wq, const float* __restrict__ bq,
    const float* __restrict__ Wk, const float* __restrict__ bk,
    const float* __restrict__ Wv, const float* __restrict__ bv)
{
    extern __shared__ unsigned short psm[];
    unsigned short* Xhi = psm;                              // 128*XSTR halves
    unsigned short* Xlo = Xhi + 128 * XSTR;
    unsigned short* Whi = Xlo + 128 * XSTR;                 // 64*WSTR
    unsigned short* Wlo = Whi + 64 * WSTR;
    float* Xs = (float*)(Wlo + 64 * WSTR);                  // staging 128x64 f32
    float* Ws = Xs + 128 * 64;                              // staging 64x64 f32

    const int which = blockIdx.y;
    const float* __restrict__ X = (which == 0) ? Xq : (which == 1) ? Xk : Xv;
    const float* __restrict__ W = (which == 0) ? Wq : (which == 1) ? Wk : Wv;
    const float* __restrict__ bias = (which == 0) ? bq : (which == 1) ? bk : bv;

    const int row0 = blockIdx.x * 128;
    const int tid = threadIdx.x;
    const int w = tid >> 5, lane = tid & 31;
    const int qr = lane >> 2, qc = lane & 3;

    // ldmatrix lane->address maps (bytes)
    const int a_lrow = ((lane >> 3) & 1) * 8 + (lane & 7);
    const int a_lcol = ((lane >> 4) & 1) * 16;
    const int b_lrow = ((lane >> 4) & 1) * 8 + (lane & 7);
    const int b_lcol = ((lane >> 3) & 1) * 16;

    const uint32_t xhi_base = smem_u32(Xhi) + (uint32_t)((w * 16 + a_lrow) * XSTR * 2 + a_lcol);
    const uint32_t xlo_base = smem_u32(Xlo) + (uint32_t)((w * 16 + a_lrow) * XSTR * 2 + a_lcol);
    const uint32_t whi_base = smem_u32(Whi) + (uint32_t)(b_lrow * WSTR * 2 + b_lcol);
    const uint32_t wlo_base = smem_u32(Wlo) + (uint32_t)(b_lrow * WSTR * 2 + b_lcol);

    // copy coords: 16B chunks
    const int cr = tid >> 4, cc4 = (tid & 15) * 4;
    const uint32_t xs_s = smem_u32(Xs);
    const uint32_t ws_s = smem_u32(Ws);

    float acc[8][4];
    #pragma unroll
    for (int i = 0; i < 8; i++)
        #pragma unroll
        for (int j = 0; j < 4; j++) acc[i][j] = 0.0f;

    // prologue: stage tile 0
    #pragma unroll
    for (int i = 0; i < 8; i++) {
        int r = cr + i * 16;
        cp_async16(xs_s + (uint32_t)((r * 64 + cc4) * 4),
                   &X[(size_t)(row0 + r) * DMODEL + cc4]);
    }
    #pragma unroll
    for (int i = 0; i < 4; i++) {
        int r = cr + i * 16;
        cp_async16(ws_s + (uint32_t)((r * 64 + cc4) * 4),
                   &W[(size_t)r * DK + cc4]);
    }
    CP_COMMIT();

    for (int kt = 0; kt < DMODEL / 64; kt++) {
        CP_WAIT0();
        __syncthreads();

        #pragma unroll
        for (int i = 0; i < 8; i++) {
            int r = cr + i * 16;
            float4 xv = *reinterpret_cast<const float4*>(&Xs[r * 64 + cc4]);
            *(uint32_t*)&Xhi[r * XSTR + cc4]     = pack_hi_pair(xv.x, xv.y);
            *(uint32_t*)&Xhi[r * XSTR + cc4 + 2] = pack_hi_pair(xv.z, xv.w);
            *(uint32_t*)&Xlo[r * XSTR + cc4]     = pack_lo_pair(xv.x, xv.y);
            *(uint32_t*)&Xlo[r * XSTR + cc4 + 2] = pack_lo_pair(xv.z, xv.w);
        }
        #pragma unroll
        for (int i = 0; i < 4; i++) {
            int r = cr + i * 16;
            float4 wv = *reinterpret_cast<const float4*>(&Ws[r * 64 + cc4]);
            Whi[(cc4 + 0) * WSTR + r] = hi16(wv.x);
            Whi[(cc4 + 1) * WSTR + r] = hi16(wv.y);
            Whi[(cc4 + 2) * WSTR + r] = hi16(wv.z);
            Whi[(cc4 + 3) * WSTR + r] = hi16(wv.w);
            Wlo[(cc4 + 0) * WSTR + r] = lo16(wv.x);
            Wlo[(cc4 + 1) * WSTR + r] = lo16(wv.y);
            Wlo[(cc4 + 2) * WSTR + r] = lo16(wv.z);
            Wlo[(cc4 + 3) * WSTR + r] = lo16(wv.w);
        }
        __syncthreads();

        if (kt + 1 < DMODEL / 64) {
            const int k0n = (kt + 1) * 64;
            #pragma unroll
            for (int i = 0; i < 8; i++) {
                int r = cr + i * 16;
                cp_async16(xs_s + (uint32_t)((r * 64 + cc4) * 4),
                           &X[(size_t)(row0 + r) * DMODEL + k0n + cc4]);
            }
            #pragma unroll
            for (int i = 0; i < 4; i++) {
                int r = cr + i * 16;
                cp_async16(ws_s + (uint32_t)((r * 64 + cc4) * 4),
                           &W[(size_t)(k0n + r) * DK + cc4]);
            }
            CP_COMMIT();
        }

        #pragma unroll
        for (int kb = 0; kb < 4; kb++) {
            const uint32_t aoff = (uint32_t)(kb * 32);
            uint32_t ah[4], al[4];
            ldsm_x4(ah, xhi_base + aoff);
            ldsm_x4(al, xlo_base + aoff);
            #pragma unroll
            for (int pr = 0; pr < 4; pr++) {
                const uint32_t boff = (uint32_t)(pr * 16 * WSTR * 2 + kb * 32);
                uint32_t bh[4], bl[4];
                ldsm_x4(bh, whi_base + boff);
                ldsm_x4(bl, wlo_base + boff);
                mma_bf16(acc[pr*2],   ah, bh[0], bh[1]);
                mma_bf16(acc[pr*2],   ah, bl[0], bl[1]);
                mma_bf16(acc[pr*2],   al, bh[0], bh[1]);
                mma_bf16(acc[pr*2+1], ah, bh[2], bh[3]);
                mma_bf16(acc[pr*2+1], ah, bl[2], bl[3]);
                mma_bf16(acc[pr*2+1], al, bh[2], bh[3]);
            }
        }
    }

    const int r0 = row0 + w * 16 + qr;
    if (which == 2) {
        // ---- fused V^T epilogue: stage V tile in smem, write transposed ----
        float* T = Xs;   // reuse staging as 128 x TSTR fp32 scratch
        const int rl = w * 16 + qr;
        #pragma unroll
        for (int nb = 0; nb < 8; nb++) {
            const int n = nb * 8 + qc * 2;
            float bx = bias[n], by = bias[n + 1];
            T[rl * TSTR + n]           = acc[nb][0] + bx;
            T[rl * TSTR + n + 1]       = acc[nb][1] + by;
            T[(rl + 8) * TSTR + n]     = acc[nb][2] + bx;
            T[(rl + 8) * TSTR + n + 1] = acc[nb][3] + by;
        }
        __syncthreads();
        const int bb = row0 / SEQ, s0 = row0 % SEQ;
        #pragma unroll
        for (int i = 0; i < 16; i++) {
            int idx = tid + i * 256;
            int d = idx >> 6, sp = idx & 63;
            float a = T[(sp * 2) * TSTR + d];
            float c = T[(sp * 2 + 1) * TSTR + d];
            size_t off = ((size_t)bb * DK + d) * SEQ + s0 + sp * 2;
            *(uint32_t*)&g_VThi[off] = pack_hi_pair(a, c);
            *(uint32_t*)&g_VTlo[off] = pack_lo_pair(a, c);
        }
    } else {
        #pragma unroll
        for (int nb = 0; nb < 8; nb++) {
            const int n = nb * 8 + qc * 2;
            float bx = bias[n], by = bias[n + 1];
            float ax = acc[nb][0] + bx, ay = acc[nb][1] + by;
            float cx = acc[nb][2] + bx, cy = acc[nb][3] + by;
            if (which == 1) {
                *(uint32_t*)&g_Khi[(size_t)r0 * DK + n]       = pack_hi_pair(ax, ay);
                *(uint32_t*)&g_Klo[(size_t)r0 * DK + n]       = pack_lo_pair(ax, ay);
                *(uint32_t*)&g_Khi[(size_t)(r0 + 8) * DK + n] = pack_hi_pair(cx, cy);
                *(uint32_t*)&g_Klo[(size_t)(r0 + 8) * DK + n] = pack_lo_pair(cx, cy);
            } else {
                float2 v0, v1;
                v0.x = ax * 0.125f; v0.y = ay * 0.125f;
                v1.x = cx * 0.125f; v1.y = cy * 0.125f;
                *reinterpret_cast<float2*>(&g_Q[(size_t)r0 * DK + n]) = v0;
                *reinterpret_cast<float2*>(&g_Q[(size_t)(r0 + 8) * DK + n]) = v1;
            }
        }
    }
}

// ---------------------------------------------------------------------------
// mma split-K causal attention with ldmatrix B-fragments (unchanged).
// ---------------------------------------------------------------------------
__global__ __launch_bounds__(128, 3) void attn_mma_kernel()
{
    extern __shared__ unsigned short asm_[];
    unsigned short* Khi = asm_;
    unsigned short* Klo = Khi + 128 * KSTR;
    unsigned short* Vhi = Klo + 128 * KSTR;
    unsigned short* Vlo = Vhi + 64 * VSTR;

    const int qtile = blockIdx.x, chunk = blockIdx.y, b = blockIdx.z;
    const int q0 = qtile * 64;
    const int kbeg = chunk * CHUNK;
    if (kbeg >= q0 + 64) return;
    const int kend = min(kbeg + CHUNK, q0 + 64);
    const int ntiles = (kend - kbeg + 127) >> 7;

    const int tid = threadIdx.x;
    const int w = tid >> 5, lane = tid & 31;
    const int qr = lane >> 2, qc = lane & 3;

    const int lrow = ((lane >> 4) & 1) * 8 + (lane & 7);
    const int lcol = ((lane >> 3) & 1) * 16;
    const uint32_t k_lsel = (uint32_t)(lrow * KSTR * 2 + lcol);
    const uint32_t v_lsel = (uint32_t)(lrow * VSTR * 2 + lcol);
    const uint32_t khi_base = smem_u32(Khi) + k_lsel;
    const uint32_t klo_base = smem_u32(Klo) + k_lsel;
    const uint32_t vhi_base = smem_u32(Vhi) + v_lsel;
    const uint32_t vlo_base = smem_u32(Vlo) + v_lsel;

    uint32_t qh[4][4], ql[4][4];
    {
        const float* Qp = g_Q + ((size_t)b * SEQ + q0 + w * 16) * DK;
        #pragma unroll
        for (int kb = 0; kb < 4; kb++) {
            const int c0 = kb * 16 + qc * 2;
            float2 x00 = *reinterpret_cast<const float2*>(&Qp[(size_t)qr * DK + c0]);
            float2 x10 = *reinterpret_cast<const float2*>(&Qp[(size_t)(qr + 8) * DK + c0]);
            float2 x01 = *reinterpret_cast<const float2*>(&Qp[(size_t)qr * DK + c0 + 8]);
            float2 x11 = *reinterpret_cast<const float2*>(&Qp[(size_t)(qr + 8) * DK + c0 + 8]);
            qh[kb][0] = pack_hi_pair(x00.x, x00.y); ql[kb][0] = pack_lo_pair(x00.x, x00.y);
            qh[kb][1] = pack_hi_pair(x10.x, x10.y); ql[kb][1] = pack_lo_pair(x10.x, x10.y);
            qh[kb][2] = pack_hi_pair(x01.x, x01.y); ql[kb][2] = pack_lo_pair(x01.x, x01.y);
            qh[kb][3] = pack_hi_pair(x11.x, x11.y); ql[kb][3] = pack_lo_pair(x11.x, x11.y);
        }
    }

    float oacc[8][4];
    #pragma unroll
    for (int i = 0; i < 8; i++)
        #pragma unroll
        for (int j = 0; j < 4; j++) oacc[i][j] = 0.0f;
    float lsum0 = 0.0f, lsum1 = 0.0f;

    const int rowlo = q0 + w * 16 + qr;
    const int rowhi = rowlo + 8;

    for (int t = 0; t < ntiles; t++) {
        const int k0 = kbeg + t * 128;
        __syncthreads();
        #pragma unroll
        for (int i = 0; i < 8; i++) {
            int idx = tid + i * 128;
            int row = idx >> 3, u = idx & 7;
            const size_t gsrc = ((size_t)b * SEQ + k0 + row) * DK;
            *reinterpret_cast<uint4*>(&Khi[row * KSTR + u * 8]) =
                reinterpret_cast<const uint4*>(g_Khi + gsrc)[u];
            *reinterpret_cast<uint4*>(&Klo[row * KSTR + u * 8]) =
                reinterpret_cast<const uint4*>(g_Klo + gsrc)[u];
        }
        #pragma unroll
        for (int i = 0; i < 8; i++) {
            int idx = tid + i * 128;
            int d = idx >> 4, u = idx & 15;
            const size_t gsrc = ((size_t)b * DK + d) * SEQ + k0;
            *reinterpret_cast<uint4*>(&Vhi[d * VSTR + u * 8]) =
                reinterpret_cast<const uint4*>(g_VThi + gsrc)[u];
            *reinterpret_cast<uint4*>(&Vlo[d * VSTR + u * 8]) =
                reinterpret_cast<const uint4*>(g_VTlo + gsrc)[u];
        }
        __syncthreads();

        float sc[16][4];
        #pragma unroll
        for (int i = 0; i < 16; i++)
            #pragma unroll
            for (int j = 0; j < 4; j++) sc[i][j] = 0.0f;

        #pragma unroll
        for (int kb = 0; kb < 4; kb++) {
            #pragma unroll
            for (int pr = 0; pr < 8; pr++) {
                const uint32_t off = (uint32_t)(pr * 16 * KSTR * 2 + kb * 32);
                uint32_t bh[4], bl[4];
                ldsm_x4(bh, khi_base + off);
                ldsm_x4(bl, klo_base + off);
                mma_bf16(sc[pr*2],   qh[kb], bh[0], bh[1]);
                mma_bf16(sc[pr*2],   qh[kb], bl[0], bl[1]);
                mma_bf16(sc[pr*2],   ql[kb], bh[0], bh[1]);
                mma_bf16(sc[pr*2+1], qh[kb], bh[2], bh[3]);
                mma_bf16(sc[pr*2+1], qh[kb], bl[2], bl[3]);
                mma_bf16(sc[pr*2+1], ql[kb], bh[2], bh[3]);
            }
        }

        #pragma unroll
        for (int nb = 0; nb < 16; nb++) {
            const int col0 = k0 + nb * 8 + qc * 2;
            float p0 = (col0     <= rowlo) ? __expf(sc[nb][0]) : 0.0f;
            float p1 = (col0 + 1 <= rowlo) ? __expf(sc[nb][1]) : 0.0f;
            float p2 = (col0     <= rowhi) ? __expf(sc[nb][2]) : 0.0f;
            float p3 = (col0 + 1 <= rowhi) ? __expf(sc[nb][3]) : 0.0f;
            lsum0 += p0 + p1;
            lsum1 += p2 + p3;
            sc[nb][0] = p0; sc[nb][1] = p1; sc[nb][2] = p2; sc[nb][3] = p3;
        }

        #pragma unroll
        for (int kb2 = 0; kb2 < 8; kb2++) {
            uint32_t pah[4], pal[4];
            pah[0] = pack_hi_pair(sc[2*kb2][0],   sc[2*kb2][1]);
            pah[1] = pack_hi_pair(sc[2*kb2][2],   sc[2*kb2][3]);
            pah[2] = pack_hi_pair(sc[2*kb2+1][0], sc[2*kb2+1][1]);
            pah[3] = pack_hi_pair(sc[2*kb2+1][2], sc[2*kb2+1][3]);
            pal[0] = pack_lo_pair(sc[2*kb2][0],   sc[2*kb2][1]);
            pal[1] = pack_lo_pair(sc[2*kb2][2],   sc[2*kb2][3]);
            pal[2] = pack_lo_pair(sc[2*kb2+1][0], sc[2*kb2+1][1]);
            pal[3] = pack_lo_pair(sc[2*kb2+1][2], sc[2*kb2+1][3]);
            #pragma unroll
            for (int pr = 0; pr < 4; pr++) {
                const uint32_t off = (uint32_t)(pr * 16 * VSTR * 2 + kb2 * 32);
                uint32_t bh[4], bl[4];
                ldsm_x4(bh, vhi_base + off);
                ldsm_x4(bl, vlo_base + off);
                mma_bf16(oacc[pr*2],   pah, bh[0], bh[1]);
                mma_bf16(oacc[pr*2],   pah, bl[0], bl[1]);
                mma_bf16(oacc[pr*2],   pal, bh[0], bh[1]);
                mma_bf16(oacc[pr*2+1], pah, bh[2], bh[3]);
                mma_bf16(oacc[pr*2+1], pah, bl[2], bl[3]);
                mma_bf16(oacc[pr*2+1], pal, bh[2], bh[3]);
            }
        }
    }

    lsum0 += __shfl_xor_sync(0xFFFFFFFFu, lsum0, 1);
    lsum0 += __shfl_xor_sync(0xFFFFFFFFu, lsum0, 2);
    lsum1 += __shfl_xor_sync(0xFFFFFFFFu, lsum1, 1);
    lsum1 += __shfl_xor_sync(0xFFFFFFFFu, lsum1, 2);

    const size_t lbase = (size_t)(chunk * BATCH + b) * SEQ + q0 + w * 16;
    if (qc == 0) {
        g_pl[lbase + qr]     = lsum0;
        g_pl[lbase + qr + 8] = lsum1;
    }

    const size_t obase = ((size_t)(chunk * BATCH + b) * SEQ + q0 + w * 16 + qr) * DK;
    #pragma unroll
    for (int db = 0; db < 8; db++) {
        const int n = db * 8 + qc * 2;
        float2 v0, v1;
        v0.x = oacc[db][0]; v0.y = oacc[db][1];
        v1.x = oacc[db][2]; v1.y = oacc[db][3];
        *reinterpret_cast<float2*>(&g_pacc[obase + n]) = v0;
        *reinterpret_cast<float2*>(&g_pacc[obase + 8 * DK + n]) = v1;
    }
}

// ---------------------------------------------------------------------------
// Combine
// ---------------------------------------------------------------------------
__global__ __launch_bounds__(256) void combine_kernel(float* __restrict__ O)
{
    const int idx = blockIdx.x * 256 + threadIdx.x;
    const int qg = idx >> 6;
    const int d  = idx & 63;
    float sa = 0.0f, sl = 0.0f;
    #pragma unroll
    for (int c = 0; c < NCHUNK; c++) {
        sa += g_pacc[((size_t)c * BATCH * SEQ + qg) * DK + d];
        sl += g_pl[(size_t)c * BATCH * SEQ + qg];
    }
    O[idx] = sa / sl;
}

extern "C" void kernel_launch(void* const* d_in, const int* in_sizes, int n_in,
                              void* d_out, int out_size)
{
    const float* qs = (const float*)d_in[0];
    const float* ks = (const float*)d_in[1];
    const float* vs = (const float*)d_in[2];
    // d_in[3] = mask — causal structure handled analytically
    const float* Wq = (const float*)d_in[4];
    const float* bq = (const float*)d_in[5];
    const float* Wk = (const float*)d_in[6];
    const float* bk = (const float*)d_in[7];
    const float* Wv = (const float*)d_in[8];
    const float* bv = (const float*)d_in[9];
    float* out = (float*)d_out;
    (void)in_sizes; (void)n_in; (void)out_size;

    const int proj_smem = (2 * 128 * XSTR + 2 * 64 * WSTR) * 2     // operands 55296
                        + (128 * 64 + 64 * 64) * 4;                // staging 49152
    const int attn_smem = (2 * 128 * KSTR + 2 * 64 * VSTR) * 2;    // 71680 B
    cudaFuncSetAttribute(proj_mma_kernel, cudaFuncAttributeMaxDynamicSharedMemorySize, proj_smem);
    cudaFuncSetAttribute(attn_mma_kernel, cudaFuncAttributeMaxDynamicSharedMemorySize, attn_smem);

    dim3 pgrid(128, 3);
    proj_mma_kernel<<<pgrid, 256, proj_smem>>>(qs, ks, vs, Wq, bq, Wk, bk, Wv, bv);

    dim3 agrid(SEQ / 64, NCHUNK, BATCH);
    attn_mma_kernel<<<agrid, 128, attn_smem>>>();

    combine_kernel<<<(BATCH * SEQ * DK) / 256, 256>>>(out);
}

// round 12
// speedup vs baseline: 1.2796x; 1.0194x over previous
#include <cuda_runtime.h>
#include <cuda_bf16.h>
#include <math.h>
#include <stdint.h>

#define DMODEL 512
#define DK     64
#define BATCH  8
#define SEQ    2048
#define NCHUNK 4
#define CHUNK  (SEQ / NCHUNK)   // 512 keys per split-K chunk

// Scratch (device globals — no allocation allowed)
__device__ float g_Q[BATCH * SEQ * DK];                  // pre-scaled by 1/8
__device__ unsigned short g_Khi[BATCH * SEQ * DK];       // bf16 trunc of K
__device__ unsigned short g_Klo[BATCH * SEQ * DK];       // bf16 residual of K
__device__ unsigned short g_VThi[BATCH * DK * SEQ];      // V^T bf16 hi
__device__ unsigned short g_VTlo[BATCH * DK * SEQ];      // V^T bf16 lo
__device__ float g_pacc[(size_t)NCHUNK * BATCH * SEQ * DK];
__device__ float g_pl[(size_t)NCHUNK * BATCH * SEQ];

// ===================== helpers =====================
__device__ __forceinline__ uint32_t pack_hi_pair(float a, float b) {
    return __byte_perm(__float_as_uint(a), __float_as_uint(b), 0x7632);
}
__device__ __forceinline__ uint32_t pack_lo_pair(float a, float b) {
    float la = a - __uint_as_float(__float_as_uint(a) & 0xFFFF0000u);
    float lb = b - __uint_as_float(__float_as_uint(b) & 0xFFFF0000u);
    uint32_t r;
    asm("cvt.rn.bf16x2.f32 %0, %1, %2;" : "=r"(r) : "f"(lb), "f"(la));
    return r;
}
__device__ __forceinline__ unsigned short hi16(float v) {
    return (unsigned short)(__float_as_uint(v) >> 16);
}
__device__ __forceinline__ unsigned short lo16(float v) {
    float r = v - __uint_as_float(__float_as_uint(v) & 0xFFFF0000u);
    unsigned short s;
    asm("cvt.rn.bf16.f32 %0, %1;" : "=h"(s) : "f"(r));
    return s;
}
__device__ __forceinline__ void mma_bf16(float* c, const uint32_t* a,
                                         uint32_t b0, uint32_t b1) {
    asm volatile(
        "mma.sync.aligned.m16n8k16.row.col.f32.bf16.bf16.f32 "
        "{%0,%1,%2,%3}, {%4,%5,%6,%7}, {%8,%9}, {%0,%1,%2,%3};"
        : "+f"(c[0]), "+f"(c[1]), "+f"(c[2]), "+f"(c[3])
        : "r"(a[0]), "r"(a[1]), "r"(a[2]), "r"(a[3]), "r"(b0), "r"(b1));
}
__device__ __forceinline__ void ldsm_x4(uint32_t* d, uint32_t saddr) {
    asm volatile("ldmatrix.sync.aligned.m8n8.x4.shared.b16 {%0,%1,%2,%3}, [%4];"
                 : "=r"(d[0]), "=r"(d[1]), "=r"(d[2]), "=r"(d[3]) : "r"(saddr));
}
__device__ __forceinline__ uint32_t smem_u32(const void* p) {
    return (uint32_t)__cvta_generic_to_shared(p);
}
__device__ __forceinline__ void cp_async16(uint32_t saddr, const void* gaddr) {
    asm volatile("cp.async.cg.shared.global [%0], [%1], 16;"
                 :: "r"(saddr), "l"(gaddr));
}
#define CP_COMMIT() asm volatile("cp.async.commit_group;" ::: "memory")
#define CP_WAIT0()  asm volatile("cp.async.wait_group 0;" ::: "memory")

// smem strides in bf16 halves: 16B-aligned rows AND conflict-free frag loads
#define KSTR 72    // K tile rows (128 x 64)
#define VSTR 136   // V^T tile rows (64 x 128)
#define WSTR 72
#define XSTG 72    // proj X staging stride in FLOATS (288B: conflict-free LDS.64)
#define TSTR 67    // fp32 transpose scratch stride

// ---------------------------------------------------------------------------
// Projection via mma. A-fragments built in registers directly from fp32
// staging (double-buffered); only W goes through bf16 operand smem.
// which: 0=Q (scaled 1/8, float out), 1=K (bf16 hi/lo out), 2=V (VT hi/lo out).
// ---------------------------------------------------------------------------
__global__ __launch_bounds__(256, 2) void proj_mma_kernel(
    const float* __restrict__ Xq, const float* __restrict__ Xk, const float* __restrict__ Xv,
    const float* __restrict__ Wq, const float* __restrict__ bq,
    const float* __restrict__ Wk, const float* __restrict__ bk,
    const float* __restrict__ Wv, const float* __restrict__ bv)
{
    extern __shared__ unsigned short psm[];
    unsigned short* Whi = psm;                              // 64*WSTR halves
    unsigned short* Wlo = Whi + 64 * WSTR;
    float* Ws = (float*)(Wlo + 64 * WSTR);                  // W staging 64x64 f32
    float* Xs = Ws + 64 * 64;                               // X staging 2 x 128 x XSTG f32

    const int which = blockIdx.y;
    const float* __restrict__ X = (which == 0) ? Xq : (which == 1) ? Xk : Xv;
    const float* __restrict__ W = (which == 0) ? Wq : (which == 1) ? Wk : Wv;
    const float* __restrict__ bias = (which == 0) ? bq : (which == 1) ? bk : bv;

    const int row0 = blockIdx.x * 128;
    const int tid = threadIdx.x;
    const int w = tid >> 5, lane = tid & 31;
    const int qr = lane >> 2, qc = lane & 3;

    // ldmatrix lane->address map for B (W^T, [n][k])
    const int b_lrow = ((lane >> 4) & 1) * 8 + (lane & 7);
    const int b_lcol = ((lane >> 3) & 1) * 16;
    const uint32_t whi_base = smem_u32(Whi) + (uint32_t)(b_lrow * WSTR * 2 + b_lcol);
    const uint32_t wlo_base = smem_u32(Wlo) + (uint32_t)(b_lrow * WSTR * 2 + b_lcol);

    // copy coords: 16B chunks
    const int cr = tid >> 4, cc4 = (tid & 15) * 4;
    const uint32_t xs_s = smem_u32(Xs);
    const uint32_t ws_s = smem_u32(Ws);
    const uint32_t xbuf_bytes = (uint32_t)(128 * XSTG * 4);

    float acc[8][4];
    #pragma unroll
    for (int i = 0; i < 8; i++)
        #pragma unroll
        for (int j = 0; j < 4; j++) acc[i][j] = 0.0f;

    // prologue: stage tile 0 into X buffer 0
    #pragma unroll
    for (int i = 0; i < 8; i++) {
        int r = cr + i * 16;
        cp_async16(xs_s + (uint32_t)((r * XSTG + cc4) * 4),
                   &X[(size_t)(row0 + r) * DMODEL + cc4]);
    }
    #pragma unroll
    for (int i = 0; i < 4; i++) {
        int r = cr + i * 16;
        cp_async16(ws_s + (uint32_t)((r * 64 + cc4) * 4),
                   &W[(size_t)r * DK + cc4]);
    }
    CP_COMMIT();

    for (int kt = 0; kt < DMODEL / 64; kt++) {
        CP_WAIT0();
        __syncthreads();

        // convert W staging -> hi/lo operand smem
        #pragma unroll
        for (int i = 0; i < 4; i++) {
            int r = cr + i * 16;
            float4 wv = *reinterpret_cast<const float4*>(&Ws[r * 64 + cc4]);
            Whi[(cc4 + 0) * WSTR + r] = hi16(wv.x);
            Whi[(cc4 + 1) * WSTR + r] = hi16(wv.y);
            Whi[(cc4 + 2) * WSTR + r] = hi16(wv.z);
            Whi[(cc4 + 3) * WSTR + r] = hi16(wv.w);
            Wlo[(cc4 + 0) * WSTR + r] = lo16(wv.x);
            Wlo[(cc4 + 1) * WSTR + r] = lo16(wv.y);
            Wlo[(cc4 + 2) * WSTR + r] = lo16(wv.z);
            Wlo[(cc4 + 3) * WSTR + r] = lo16(wv.w);
        }
        __syncthreads();

        // stage tile kt+1 while mma runs (X into the other buffer)
        if (kt + 1 < DMODEL / 64) {
            const int k0n = (kt + 1) * 64;
            const uint32_t xdst = xs_s + ((kt + 1) & 1) * xbuf_bytes;
            #pragma unroll
            for (int i = 0; i < 8; i++) {
                int r = cr + i * 16;
                cp_async16(xdst + (uint32_t)((r * XSTG + cc4) * 4),
                           &X[(size_t)(row0 + r) * DMODEL + k0n + cc4]);
            }
            #pragma unroll
            for (int i = 0; i < 4; i++) {
                int r = cr + i * 16;
                cp_async16(ws_s + (uint32_t)((r * 64 + cc4) * 4),
                           &W[(size_t)(k0n + r) * DK + cc4]);
            }
            CP_COMMIT();
        }

        const float* Xc = Xs + (kt & 1) * (128 * XSTG) + (w * 16 + qr) * XSTG;

        #pragma unroll
        for (int kb = 0; kb < 4; kb++) {
            const int c0 = kb * 16 + qc * 2;
            float2 x00 = *reinterpret_cast<const float2*>(&Xc[c0]);
            float2 x10 = *reinterpret_cast<const float2*>(&Xc[8 * XSTG + c0]);
            float2 x01 = *reinterpret_cast<const float2*>(&Xc[c0 + 8]);
            float2 x11 = *reinterpret_cast<const float2*>(&Xc[8 * XSTG + c0 + 8]);
            uint32_t ah[4], al[4];
            ah[0] = pack_hi_pair(x00.x, x00.y); al[0] = pack_lo_pair(x00.x, x00.y);
            ah[1] = pack_hi_pair(x10.x, x10.y); al[1] = pack_lo_pair(x10.x, x10.y);
            ah[2] = pack_hi_pair(x01.x, x01.y); al[2] = pack_lo_pair(x01.x, x01.y);
            ah[3] = pack_hi_pair(x11.x, x11.y); al[3] = pack_lo_pair(x11.x, x11.y);
            #pragma unroll
            for (int pr = 0; pr < 4; pr++) {
                const uint32_t boff = (uint32_t)(pr * 16 * WSTR * 2 + kb * 32);
                uint32_t bh[4], bl[4];
                ldsm_x4(bh, whi_base + boff);
                ldsm_x4(bl, wlo_base + boff);
                mma_bf16(acc[pr*2],   ah, bh[0], bh[1]);
                mma_bf16(acc[pr*2],   ah, bl[0], bl[1]);
                mma_bf16(acc[pr*2],   al, bh[0], bh[1]);
                mma_bf16(acc[pr*2+1], ah, bh[2], bh[3]);
                mma_bf16(acc[pr*2+1], ah, bl[2], bl[3]);
                mma_bf16(acc[pr*2+1], al, bh[2], bh[3]);
            }
        }
    }

    const int r0 = row0 + w * 16 + qr;
    if (which == 2) {
        // ---- fused V^T epilogue ----
        __syncthreads();              // mma done everywhere; staging reusable
        float* T = Xs;                // 128 x TSTR fp32 scratch
        const int rl = w * 16 + qr;
        #pragma unroll
        for (int nb = 0; nb < 8; nb++) {
            const int n = nb * 8 + qc * 2;
            float bx = bias[n], by = bias[n + 1];
            T[rl * TSTR + n]           = acc[nb][0] + bx;
            T[rl * TSTR + n + 1]       = acc[nb][1] + by;
            T[(rl + 8) * TSTR + n]     = acc[nb][2] + bx;
            T[(rl + 8) * TSTR + n + 1] = acc[nb][3] + by;
        }
        __syncthreads();
        const int bb = row0 / SEQ, s0 = row0 % SEQ;
        #pragma unroll
        for (int i = 0; i < 16; i++) {
            int idx = tid + i * 256;
            int d = idx >> 6, sp = idx & 63;
            float a = T[(sp * 2) * TSTR + d];
            float c = T[(sp * 2 + 1) * TSTR + d];
            size_t off = ((size_t)bb * DK + d) * SEQ + s0 + sp * 2;
            *(uint32_t*)&g_VThi[off] = pack_hi_pair(a, c);
            *(uint32_t*)&g_VTlo[off] = pack_lo_pair(a, c);
        }
    } else {
        #pragma unroll
        for (int nb = 0; nb < 8; nb++) {
            const int n = nb * 8 + qc * 2;
            float bx = bias[n], by = bias[n + 1];
            float ax = acc[nb][0] + bx, ay = acc[nb][1] + by;
            float cx = acc[nb][2] + bx, cy = acc[nb][3] + by;
            if (which == 1) {
                *(uint32_t*)&g_Khi[(size_t)r0 * DK + n]       = pack_hi_pair(ax, ay);
                *(uint32_t*)&g_Klo[(size_t)r0 * DK + n]       = pack_lo_pair(ax, ay);
                *(uint32_t*)&g_Khi[(size_t)(r0 + 8) * DK + n] = pack_hi_pair(cx, cy);
                *(uint32_t*)&g_Klo[(size_t)(r0 + 8) * DK + n] = pack_lo_pair(cx, cy);
            } else {
                float2 v0, v1;
                v0.x = ax * 0.125f; v0.y = ay * 0.125f;
                v1.x = cx * 0.125f; v1.y = cy * 0.125f;
                *reinterpret_cast<float2*>(&g_Q[(size_t)r0 * DK + n]) = v0;
                *reinterpret_cast<float2*>(&g_Q[(size_t)(r0 + 8) * DK + n]) = v1;
            }
        }
    }
}

// ---------------------------------------------------------------------------
// mma split-K causal attention with ldmatrix B-fragments (unchanged).
// ---------------------------------------------------------------------------
__global__ __launch_bounds__(128, 3) void attn_mma_kernel()
{
    extern __shared__ unsigned short asm_[];
    unsigned short* Khi = asm_;
    unsigned short* Klo = Khi + 128 * KSTR;
    unsigned short* Vhi = Klo + 128 * KSTR;
    unsigned short* Vlo = Vhi + 64 * VSTR;

    const int qtile = blockIdx.x, chunk = blockIdx.y, b = blockIdx.z;
    const int q0 = qtile * 64;
    const int kbeg = chunk * CHUNK;
    if (kbeg >= q0 + 64) return;
    const int kend = min(kbeg + CHUNK, q0 + 64);
    const int ntiles = (kend - kbeg + 127) >> 7;

    const int tid = threadIdx.x;
    const int w = tid >> 5, lane = tid & 31;
    const int qr = lane >> 2, qc = lane & 3;

    const int lrow = ((lane >> 4) & 1) * 8 + (lane & 7);
    const int lcol = ((lane >> 3) & 1) * 16;
    const uint32_t k_lsel = (uint32_t)(lrow * KSTR * 2 + lcol);
    const uint32_t v_lsel = (uint32_t)(lrow * VSTR * 2 + lcol);
    const uint32_t khi_base = smem_u32(Khi) + k_lsel;
    const uint32_t klo_base = smem_u32(Klo) + k_lsel;
    const uint32_t vhi_base = smem_u32(Vhi) + v_lsel;
    const uint32_t vlo_base = smem_u32(Vlo) + v_lsel;

    uint32_t qh[4][4], ql[4][4];
    {
        const float* Qp = g_Q + ((size_t)b * SEQ + q0 + w * 16) * DK;
        #pragma unroll
        for (int kb = 0; kb < 4; kb++) {
            const int c0 = kb * 16 + qc * 2;
            float2 x00 = *reinterpret_cast<const float2*>(&Qp[(size_t)qr * DK + c0]);
            float2 x10 = *reinterpret_cast<const float2*>(&Qp[(size_t)(qr + 8) * DK + c0]);
            float2 x01 = *reinterpret_cast<const float2*>(&Qp[(size_t)qr * DK + c0 + 8]);
            float2 x11 = *reinterpret_cast<const float2*>(&Qp[(size_t)(qr + 8) * DK + c0 + 8]);
            qh[kb][0] = pack_hi_pair(x00.x, x00.y); ql[kb][0] = pack_lo_pair(x00.x, x00.y);
            qh[kb][1] = pack_hi_pair(x10.x, x10.y); ql[kb][1] = pack_lo_pair(x10.x, x10.y);
            qh[kb][2] = pack_hi_pair(x01.x, x01.y); ql[kb][2] = pack_lo_pair(x01.x, x01.y);
            qh[kb][3] = pack_hi_pair(x11.x, x11.y); ql[kb][3] = pack_lo_pair(x11.x, x11.y);
        }
    }

    float oacc[8][4];
    #pragma unroll
    for (int i = 0; i < 8; i++)
        #pragma unroll
        for (int j = 0; j < 4; j++) oacc[i][j] = 0.0f;
    float lsum0 = 0.0f, lsum1 = 0.0f;

    const int rowlo = q0 + w * 16 + qr;
    const int rowhi = rowlo + 8;

    for (int t = 0; t < ntiles; t++) {
        const int k0 = kbeg + t * 128;
        __syncthreads();
        #pragma unroll
        for (int i = 0; i < 8; i++) {
            int idx = tid + i * 128;
            int row = idx >> 3, u = idx & 7;
            const size_t gsrc = ((size_t)b * SEQ + k0 + row) * DK;
            *reinterpret_cast<uint4*>(&Khi[row * KSTR + u * 8]) =
                reinterpret_cast<const uint4*>(g_Khi + gsrc)[u];
            *reinterpret_cast<uint4*>(&Klo[row * KSTR + u * 8]) =
                reinterpret_cast<const uint4*>(g_Klo + gsrc)[u];
        }
        #pragma unroll
        for (int i = 0; i < 8; i++) {
            int idx = tid + i * 128;
            int d = idx >> 4, u = idx & 15;
            const size_t gsrc = ((size_t)b * DK + d) * SEQ + k0;
            *reinterpret_cast<uint4*>(&Vhi[d * VSTR + u * 8]) =
                reinterpret_cast<const uint4*>(g_VThi + gsrc)[u];
            *reinterpret_cast<uint4*>(&Vlo[d * VSTR + u * 8]) =
                reinterpret_cast<const uint4*>(g_VTlo + gsrc)[u];
        }
        __syncthreads();

        float sc[16][4];
        #pragma unroll
        for (int i = 0; i < 16; i++)
            #pragma unroll
            for (int j = 0; j < 4; j++) sc[i][j] = 0.0f;

        #pragma unroll
        for (int kb = 0; kb < 4; kb++) {
            #pragma unroll
            for (int pr = 0; pr < 8; pr++) {
                const uint32_t off = (uint32_t)(pr * 16 * KSTR * 2 + kb * 32);
                uint32_t bh[4], bl[4];
                ldsm_x4(bh, khi_base + off);
                ldsm_x4(bl, klo_base + off);
                mma_bf16(sc[pr*2],   qh[kb], bh[0], bh[1]);
                mma_bf16(sc[pr*2],   qh[kb], bl[0], bl[1]);
                mma_bf16(sc[pr*2],   ql[kb], bh[0], bh[1]);
                mma_bf16(sc[pr*2+1], qh[kb], bh[2], bh[3]);
                mma_bf16(sc[pr*2+1], qh[kb], bl[2], bl[3]);
                mma_bf16(sc[pr*2+1], ql[kb], bh[2], bh[3]);
            }
        }

        #pragma unroll
        for (int nb = 0; nb < 16; nb++) {
            const int col0 = k0 + nb * 8 + qc * 2;
            float p0 = (col0     <= rowlo) ? __expf(sc[nb][0]) : 0.0f;
            float p1 = (col0 + 1 <= rowlo) ? __expf(sc[nb][1]) : 0.0f;
            float p2 = (col0     <= rowhi) ? __expf(sc[nb][2]) : 0.0f;
            float p3 = (col0 + 1 <= rowhi) ? __expf(sc[nb][3]) : 0.0f;
            lsum0 += p0 + p1;
            lsum1 += p2 + p3;
            sc[nb][0] = p0; sc[nb][1] = p1; sc[nb][2] = p2; sc[nb][3] = p3;
        }

        #pragma unroll
        for (int kb2 = 0; kb2 < 8; kb2++) {
            uint32_t pah[4], pal[4];
            pah[0] = pack_hi_pair(sc[2*kb2][0],   sc[2*kb2][1]);
            pah[1] = pack_hi_pair(sc[2*kb2][2],   sc[2*kb2][3]);
            pah[2] = pack_hi_pair(sc[2*kb2+1][0], sc[2*kb2+1][1]);
            pah[3] = pack_hi_pair(sc[2*kb2+1][2], sc[2*kb2+1][3]);
            pal[0] = pack_lo_pair(sc[2*kb2][0],   sc[2*kb2][1]);
            pal[1] = pack_lo_pair(sc[2*kb2][2],   sc[2*kb2][3]);
            pal[2] = pack_lo_pair(sc[2*kb2+1][0], sc[2*kb2+1][1]);
            pal[3] = pack_lo_pair(sc[2*kb2+1][2], sc[2*kb2+1][3]);
            #pragma unroll
            for (int pr = 0; pr < 4; pr++) {
                const uint32_t off = (uint32_t)(pr * 16 * VSTR * 2 + kb2 * 32);
                uint32_t bh[4], bl[4];
                ldsm_x4(bh, vhi_base + off);
                ldsm_x4(bl, vlo_base + off);
                mma_bf16(oacc[pr*2],   pah, bh[0], bh[1]);
                mma_bf16(oacc[pr*2],   pah, bl[0], bl[1]);
                mma_bf16(oacc[pr*2],   pal, bh[0], bh[1]);
                mma_bf16(oacc[pr*2+1], pah, bh[2], bh[3]);
                mma_bf16(oacc[pr*2+1], pah, bl[2], bl[3]);
                mma_bf16(oacc[pr*2+1], pal, bh[2], bh[3]);
            }
        }
    }

    lsum0 += __shfl_xor_sync(0xFFFFFFFFu, lsum0, 1);
    lsum0 += __shfl_xor_sync(0xFFFFFFFFu, lsum0, 2);
    lsum1 += __shfl_xor_sync(0xFFFFFFFFu, lsum1, 1);
    lsum1 += __shfl_xor_sync(0xFFFFFFFFu, lsum1, 2);

    const size_t lbase = (size_t)(chunk * BATCH + b) * SEQ + q0 + w * 16;
    if (qc == 0) {
        g_pl[lbase + qr]     = lsum0;
        g_pl[lbase + qr + 8] = lsum1;
    }

    const size_t obase = ((size_t)(chunk * BATCH + b) * SEQ + q0 + w * 16 + qr) * DK;
    #pragma unroll
    for (int db = 0; db < 8; db++) {
        const int n = db * 8 + qc * 2;
        float2 v0, v1;
        v0.x = oacc[db][0]; v0.y = oacc[db][1];
        v1.x = oacc[db][2]; v1.y = oacc[db][3];
        *reinterpret_cast<float2*>(&g_pacc[obase + n]) = v0;
        *reinterpret_cast<float2*>(&g_pacc[obase + 8 * DK + n]) = v1;
    }
}

// ---------------------------------------------------------------------------
// Combine
// ---------------------------------------------------------------------------
__global__ __launch_bounds__(256) void combine_kernel(float* __restrict__ O)
{
    const int idx = blockIdx.x * 256 + threadIdx.x;
    const int qg = idx >> 6;
    const int d  = idx & 63;
    float sa = 0.0f, sl = 0.0f;
    #pragma unroll
    for (int c = 0; c < NCHUNK; c++) {
        sa += g_pacc[((size_t)c * BATCH * SEQ + qg) * DK + d];
        sl += g_pl[(size_t)c * BATCH * SEQ + qg];
    }
    O[idx] = sa / sl;
}

extern "C" void kernel_launch(void* const* d_in, const int* in_sizes, int n_in,
                              void* d_out, int out_size)
{
    const float* qs = (const float*)d_in[0];
    const float* ks = (const float*)d_in[1];
    const float* vs = (const float*)d_in[2];
    // d_in[3] = mask — causal structure handled analytically
    const float* Wq = (const float*)d_in[4];
    const float* bq = (const float*)d_in[5];
    const float* Wk = (const float*)d_in[6];
    const float* bk = (const float*)d_in[7];
    const float* Wv = (const float*)d_in[8];
    const float* bv = (const float*)d_in[9];
    float* out = (float*)d_out;
    (void)in_sizes; (void)n_in; (void)out_size;

    const int proj_smem = (2 * 64 * WSTR) * 2              // W operands 18432
                        + 64 * 64 * 4                      // W staging  16384
                        + 2 * 128 * XSTG * 4;              // X staging  73728
    const int attn_smem = (2 * 128 * KSTR + 2 * 64 * VSTR) * 2;    // 71680 B
    cudaFuncSetAttribute(proj_mma_kernel, cudaFuncAttributeMaxDynamicSharedMemorySize, proj_smem);
    cudaFuncSetAttribute(attn_mma_kernel, cudaFuncAttributeMaxDynamicSharedMemorySize, attn_smem);

    dim3 pgrid(128, 3);
    proj_mma_kernel<<<pgrid, 256, proj_smem>>>(qs, ks, vs, Wq, bq, Wk, bk, Wv, bv);

    dim3 agrid(SEQ / 64, NCHUNK, BATCH);
    attn_mma_kernel<<<agrid, 128, attn_smem>>>();

    combine_kernel<<<(BATCH * SEQ * DK) / 256, 256>>>(out);
}

// round 13
// speedup vs baseline: 1.4618x; 1.1424x over previous
#include <cuda_runtime.h>
#include <cuda_bf16.h>
#include <math.h>
#include <stdint.h>

#define DMODEL 512
#define DK     64
#define BATCH  8
#define SEQ    2048
#define NCHUNK 4
#define CHUNK  (SEQ / NCHUNK)   // 512 keys per split-K chunk

// Scratch (device globals — no allocation allowed)
__device__ float g_Q[BATCH * SEQ * DK];                  // pre-scaled by 1/8
__device__ unsigned short g_Khi[BATCH * SEQ * DK];       // bf16 trunc of K
__device__ unsigned short g_Klo[BATCH * SEQ * DK];       // bf16 residual of K
__device__ unsigned short g_VThi[BATCH * DK * SEQ];      // V^T bf16 hi
__device__ unsigned short g_VTlo[BATCH * DK * SEQ];      // V^T bf16 lo
__device__ unsigned short g_Wphi[3 * 8 * 64 * 64];       // W^T bf16 hi [which][kt][n][k]
__device__ unsigned short g_Wplo[3 * 8 * 64 * 64];       // W^T bf16 lo
__device__ float g_pacc[(size_t)NCHUNK * BATCH * SEQ * DK];
__device__ float g_pl[(size_t)NCHUNK * BATCH * SEQ];

// ===================== helpers =====================
__device__ __forceinline__ uint32_t pack_hi_pair(float a, float b) {
    return __byte_perm(__float_as_uint(a), __float_as_uint(b), 0x7632);
}
__device__ __forceinline__ uint32_t pack_lo_pair(float a, float b) {
    float la = a - __uint_as_float(__float_as_uint(a) & 0xFFFF0000u);
    float lb = b - __uint_as_float(__float_as_uint(b) & 0xFFFF0000u);
    uint32_t r;
    asm("cvt.rn.bf16x2.f32 %0, %1, %2;" : "=r"(r) : "f"(lb), "f"(la));
    return r;
}
__device__ __forceinline__ unsigned short hi16(float v) {
    return (unsigned short)(__float_as_uint(v) >> 16);
}
__device__ __forceinline__ unsigned short lo16(float v) {
    float r = v - __uint_as_float(__float_as_uint(v) & 0xFFFF0000u);
    unsigned short s;
    asm("cvt.rn.bf16.f32 %0, %1;" : "=h"(s) : "f"(r));
    return s;
}
__device__ __forceinline__ void mma_bf16(float* c, const uint32_t* a,
                                         uint32_t b0, uint32_t b1) {
    asm volatile(
        "mma.sync.aligned.m16n8k16.row.col.f32.bf16.bf16.f32 "
        "{%0,%1,%2,%3}, {%4,%5,%6,%7}, {%8,%9}, {%0,%1,%2,%3};"
        : "+f"(c[0]), "+f"(c[1]), "+f"(c[2]), "+f"(c[3])
        : "r"(a[0]), "r"(a[1]), "r"(a[2]), "r"(a[3]), "r"(b0), "r"(b1));
}
__device__ __forceinline__ void ldsm_x4(uint32_t* d, uint32_t saddr) {
    asm volatile("ldmatrix.sync.aligned.m8n8.x4.shared.b16 {%0,%1,%2,%3}, [%4];"
                 : "=r"(d[0]), "=r"(d[1]), "=r"(d[2]), "=r"(d[3]) : "r"(saddr));
}
__device__ __forceinline__ uint32_t smem_u32(const void* p) {
    return (uint32_t)__cvta_generic_to_shared(p);
}
__device__ __forceinline__ void cp_async16(uint32_t saddr, const void* gaddr) {
    asm volatile("cp.async.cg.shared.global [%0], [%1], 16;"
                 :: "r"(saddr), "l"(gaddr));
}
#define CP_COMMIT() asm volatile("cp.async.commit_group;" ::: "memory")
#define CP_WAIT0()  asm volatile("cp.async.wait_group 0;" ::: "memory")

// smem strides
#define KSTR 72    // attn K tile rows (bf16 halves)
#define VSTR 136   // attn V^T tile rows
#define WSTR 72    // proj W operand rows (bf16 halves)
#define XSTG 68    // proj X staging stride in FLOATS (272B: conflict-free LDS.64)
#define TSTR 67    // fp32 transpose scratch stride

// ---------------------------------------------------------------------------
// W precompute: W[k][n] fp32 -> g_Wp{hi,lo}[which][kt][n][k] bf16 (B layout)
// Grid (8, 3), block 256.
// ---------------------------------------------------------------------------
__global__ __launch_bounds__(256) void w_convert_kernel(
    const float* __restrict__ Wq, const float* __restrict__ Wk, const float* __restrict__ Wv)
{
    const int kt = blockIdx.x, which = blockIdx.y;
    const float* __restrict__ W = (which == 0) ? Wq : (which == 1) ? Wk : Wv;
    const int base = (which * 8 + kt) * 64 * 64;
    for (int i = 0; i < 16; i++) {
        int e = threadIdx.x + i * 256;
        int n = e >> 6, r = e & 63;
        float v = W[(size_t)(kt * 64 + r) * DK + n];
        g_Wphi[base + n * 64 + r] = hi16(v);
        g_Wplo[base + n * 64 + r] = lo16(v);
    }
}

// ---------------------------------------------------------------------------
// Projection via mma. X: fp32 staging (double-buffered) -> register A-frags.
// W: preconverted bf16 hi/lo, double-buffered direct cp.async -> ldmatrix.
// No convert pass in the k-loop: wait -> sync -> issue(t+1) -> mma.
// which: 0=Q (scaled 1/8, float out), 1=K (bf16 hi/lo out), 2=V (VT hi/lo out).
// ---------------------------------------------------------------------------
__global__ __launch_bounds__(256, 2) void proj_mma_kernel(
    const float* __restrict__ Xq, const float* __restrict__ Xk, const float* __restrict__ Xv,
    const float* __restrict__ bq, const float* __restrict__ bk, const float* __restrict__ bv)
{
    extern __shared__ unsigned short psm[];
    unsigned short* Wh = psm;                               // 2 x 64*WSTR halves
    unsigned short* Wl = Wh + 2 * 64 * WSTR;
    float* Xs = (float*)(Wl + 2 * 64 * WSTR);               // 2 x 128*XSTG f32

    const int which = blockIdx.y;
    const float* __restrict__ X = (which == 0) ? Xq : (which == 1) ? Xk : Xv;
    const float* __restrict__ bias = (which == 0) ? bq : (which == 1) ? bk : bv;

    const int row0 = blockIdx.x * 128;
    const int tid = threadIdx.x;
    const int w = tid >> 5, lane = tid & 31;
    const int qr = lane >> 2, qc = lane & 3;

    // ldmatrix lane->address map for B (W^T, [n][k])
    const int b_lrow = ((lane >> 4) & 1) * 8 + (lane & 7);
    const int b_lcol = ((lane >> 3) & 1) * 16;
    const uint32_t wh_base = smem_u32(Wh) + (uint32_t)(b_lrow * WSTR * 2 + b_lcol);
    const uint32_t wl_base = smem_u32(Wl) + (uint32_t)(b_lrow * WSTR * 2 + b_lcol);
    const uint32_t WBUF = (uint32_t)(64 * WSTR * 2);        // bytes per W buffer

    // copy coords
    const int cr = tid >> 4, cc4 = (tid & 15) * 4;          // X: 16B chunks
    const int wn = tid >> 3, wu = tid & 7;                  // W: row n, chunk u (512 chunks, 2/thread)
    const uint32_t xs_s = smem_u32(Xs);
    const uint32_t wh_s = smem_u32(Wh);
    const uint32_t wl_s = smem_u32(Wl);
    const uint32_t xbuf_bytes = (uint32_t)(128 * XSTG * 4);

    float acc[8][4];
    #pragma unroll
    for (int i = 0; i < 8; i++)
        #pragma unroll
        for (int j = 0; j < 4; j++) acc[i][j] = 0.0f;

    const int wgbase = which * 8 * 64 * 64;

    // prologue: stage tile 0
    #pragma unroll
    for (int i = 0; i < 8; i++) {
        int r = cr + i * 16;
        cp_async16(xs_s + (uint32_t)((r * XSTG + cc4) * 4),
                   &X[(size_t)(row0 + r) * DMODEL + cc4]);
    }
    #pragma unroll
    for (int i = 0; i < 2; i++) {
        int c = tid + i * 256;                 // 0..511
        int n = c >> 3, u = c & 7;
        cp_async16(wh_s + (uint32_t)(n * WSTR * 2 + u * 16),
                   g_Wphi + wgbase + n * 64 + u * 8);
        cp_async16(wl_s + (uint32_t)(n * WSTR * 2 + u * 16),
                   g_Wplo + wgbase + n * 64 + u * 8);
    }
    CP_COMMIT();

    for (int kt = 0; kt < DMODEL / 64; kt++) {
        CP_WAIT0();
        __syncthreads();

        // stage tile kt+1 while mma(kt) runs
        if (kt + 1 < DMODEL / 64) {
            const int k0n = (kt + 1) * 64;
            const uint32_t bsel = (uint32_t)((kt + 1) & 1);
            const uint32_t xdst = xs_s + bsel * xbuf_bytes;
            #pragma unroll
            for (int i = 0; i < 8; i++) {
                int r = cr + i * 16;
                cp_async16(xdst + (uint32_t)((r * XSTG + cc4) * 4),
                           &X[(size_t)(row0 + r) * DMODEL + k0n + cc4]);
            }
            const int wtile = wgbase + (kt + 1) * 64 * 64;
            #pragma unroll
            for (int i = 0; i < 2; i++) {
                int c = tid + i * 256;
                int n = c >> 3, u = c & 7;
                cp_async16(wh_s + bsel * WBUF + (uint32_t)(n * WSTR * 2 + u * 16),
                           g_Wphi + wtile + n * 64 + u * 8);
                cp_async16(wl_s + bsel * WBUF + (uint32_t)(n * WSTR * 2 + u * 16),
                           g_Wplo + wtile + n * 64 + u * 8);
            }
            CP_COMMIT();
        }

        const float* Xc = Xs + (kt & 1) * (128 * XSTG) + (w * 16 + qr) * XSTG;
        const uint32_t wb = (uint32_t)(kt & 1) * WBUF;

        #pragma unroll
        for (int kb = 0; kb < 4; kb++) {
            const int c0 = kb * 16 + qc * 2;
            float2 x00 = *reinterpret_cast<const float2*>(&Xc[c0]);
            float2 x10 = *reinterpret_cast<const float2*>(&Xc[8 * XSTG + c0]);
            float2 x01 = *reinterpret_cast<const float2*>(&Xc[c0 + 8]);
            float2 x11 = *reinterpret_cast<const float2*>(&Xc[8 * XSTG + c0 + 8]);
            uint32_t ah[4], al[4];
            ah[0] = pack_hi_pair(x00.x, x00.y); al[0] = pack_lo_pair(x00.x, x00.y);
            ah[1] = pack_hi_pair(x10.x, x10.y); al[1] = pack_lo_pair(x10.x, x10.y);
            ah[2] = pack_hi_pair(x01.x, x01.y); al[2] = pack_lo_pair(x01.x, x01.y);
            ah[3] = pack_hi_pair(x11.x, x11.y); al[3] = pack_lo_pair(x11.x, x11.y);
            #pragma unroll
            for (int pr = 0; pr < 4; pr++) {
                const uint32_t boff = wb + (uint32_t)(pr * 16 * WSTR * 2 + kb * 32);
                uint32_t bh[4], bl[4];
                ldsm_x4(bh, wh_base + boff);
                ldsm_x4(bl, wl_base + boff);
                mma_bf16(acc[pr*2],   ah, bh[0], bh[1]);
                mma_bf16(acc[pr*2],   ah, bl[0], bl[1]);
                mma_bf16(acc[pr*2],   al, bh[0], bh[1]);
                mma_bf16(acc[pr*2+1], ah, bh[2], bh[3]);
                mma_bf16(acc[pr*2+1], ah, bl[2], bl[3]);
                mma_bf16(acc[pr*2+1], al, bh[2], bh[3]);
            }
        }
    }

    const int r0 = row0 + w * 16 + qr;
    if (which == 2) {
        // ---- fused V^T epilogue ----
        __syncthreads();
        float* T = Xs;                // 128 x TSTR fp32 scratch
        const int rl = w * 16 + qr;
        #pragma unroll
        for (int nb = 0; nb < 8; nb++) {
            const int n = nb * 8 + qc * 2;
            float bx = bias[n], by = bias[n + 1];
            T[rl * TSTR + n]           = acc[nb][0] + bx;
            T[rl * TSTR + n + 1]       = acc[nb][1] + by;
            T[(rl + 8) * TSTR + n]     = acc[nb][2] + bx;
            T[(rl + 8) * TSTR + n + 1] = acc[nb][3] + by;
        }
        __syncthreads();
        const int bb = row0 / SEQ, s0 = row0 % SEQ;
        #pragma unroll
        for (int i = 0; i < 16; i++) {
            int idx = tid + i * 256;
            int d = idx >> 6, sp = idx & 63;
            float a = T[(sp * 2) * TSTR + d];
            float c = T[(sp * 2 + 1) * TSTR + d];
            size_t off = ((size_t)bb * DK + d) * SEQ + s0 + sp * 2;
            *(uint32_t*)&g_VThi[off] = pack_hi_pair(a, c);
            *(uint32_t*)&g_VTlo[off] = pack_lo_pair(a, c);
        }
    } else {
        #pragma unroll
        for (int nb = 0; nb < 8; nb++) {
            const int n = nb * 8 + qc * 2;
            float bx = bias[n], by = bias[n + 1];
            float ax = acc[nb][0] + bx, ay = acc[nb][1] + by;
            float cx = acc[nb][2] + bx, cy = acc[nb][3] + by;
            if (which == 1) {
                *(uint32_t*)&g_Khi[(size_t)r0 * DK + n]       = pack_hi_pair(ax, ay);
                *(uint32_t*)&g_Klo[(size_t)r0 * DK + n]       = pack_lo_pair(ax, ay);
                *(uint32_t*)&g_Khi[(size_t)(r0 + 8) * DK + n] = pack_hi_pair(cx, cy);
                *(uint32_t*)&g_Klo[(size_t)(r0 + 8) * DK + n] = pack_lo_pair(cx, cy);
            } else {
                float2 v0, v1;
                v0.x = ax * 0.125f; v0.y = ay * 0.125f;
                v1.x = cx * 0.125f; v1.y = cy * 0.125f;
                *reinterpret_cast<float2*>(&g_Q[(size_t)r0 * DK + n]) = v0;
                *reinterpret_cast<float2*>(&g_Q[(size_t)(r0 + 8) * DK + n]) = v1;
            }
        }
    }
}

// ---------------------------------------------------------------------------
// mma split-K causal attention with ldmatrix B-fragments (unchanged).
// ---------------------------------------------------------------------------
__global__ __launch_bounds__(128, 3) void attn_mma_kernel()
{
    extern __shared__ unsigned short asm_[];
    unsigned short* Khi = asm_;
    unsigned short* Klo = Khi + 128 * KSTR;
    unsigned short* Vhi = Klo + 128 * KSTR;
    unsigned short* Vlo = Vhi + 64 * VSTR;

    const int qtile = blockIdx.x, chunk = blockIdx.y, b = blockIdx.z;
    const int q0 = qtile * 64;
    const int kbeg = chunk * CHUNK;
    if (kbeg >= q0 + 64) return;
    const int kend = min(kbeg + CHUNK, q0 + 64);
    const int ntiles = (kend - kbeg + 127) >> 7;

    const int tid = threadIdx.x;
    const int w = tid >> 5, lane = tid & 31;
    const int qr = lane >> 2, qc = lane & 3;

    const int lrow = ((lane >> 4) & 1) * 8 + (lane & 7);
    const int lcol = ((lane >> 3) & 1) * 16;
    const uint32_t k_lsel = (uint32_t)(lrow * KSTR * 2 + lcol);
    const uint32_t v_lsel = (uint32_t)(lrow * VSTR * 2 + lcol);
    const uint32_t khi_base = smem_u32(Khi) + k_lsel;
    const uint32_t klo_base = smem_u32(Klo) + k_lsel;
    const uint32_t vhi_base = smem_u32(Vhi) + v_lsel;
    const uint32_t vlo_base = smem_u32(Vlo) + v_lsel;

    uint32_t qh[4][4], ql[4][4];
    {
        const float* Qp = g_Q + ((size_t)b * SEQ + q0 + w * 16) * DK;
        #pragma unroll
        for (int kb = 0; kb < 4; kb++) {
            const int c0 = kb * 16 + qc * 2;
            float2 x00 = *reinterpret_cast<const float2*>(&Qp[(size_t)qr * DK + c0]);
            float2 x10 = *reinterpret_cast<const float2*>(&Qp[(size_t)(qr + 8) * DK + c0]);
            float2 x01 = *reinterpret_cast<const float2*>(&Qp[(size_t)qr * DK + c0 + 8]);
            float2 x11 = *reinterpret_cast<const float2*>(&Qp[(size_t)(qr + 8) * DK + c0 + 8]);
            qh[kb][0] = pack_hi_pair(x00.x, x00.y); ql[kb][0] = pack_lo_pair(x00.x, x00.y);
            qh[kb][1] = pack_hi_pair(x10.x, x10.y); ql[kb][1] = pack_lo_pair(x10.x, x10.y);
            qh[kb][2] = pack_hi_pair(x01.x, x01.y); ql[kb][2] = pack_lo_pair(x01.x, x01.y);
            qh[kb][3] = pack_hi_pair(x11.x, x11.y); ql[kb][3] = pack_lo_pair(x11.x, x11.y);
        }
    }

    float oacc[8][4];
    #pragma unroll
    for (int i = 0; i < 8; i++)
        #pragma unroll
        for (int j = 0; j < 4; j++) oacc[i][j] = 0.0f;
    float lsum0 = 0.0f, lsum1 = 0.0f;

    const int rowlo = q0 + w * 16 + qr;
    const int rowhi = rowlo + 8;

    for (int t = 0; t < ntiles; t++) {
        const int k0 = kbeg + t * 128;
        __syncthreads();
        #pragma unroll
        for (int i = 0; i < 8; i++) {
            int idx = tid + i * 128;
            int row = idx >> 3, u = idx & 7;
            const size_t gsrc = ((size_t)b * SEQ + k0 + row) * DK;
            *reinterpret_cast<uint4*>(&Khi[row * KSTR + u * 8]) =
                reinterpret_cast<const uint4*>(g_Khi + gsrc)[u];
            *reinterpret_cast<uint4*>(&Klo[row * KSTR + u * 8]) =
                reinterpret_cast<const uint4*>(g_Klo + gsrc)[u];
        }
        #pragma unroll
        for (int i = 0; i < 8; i++) {
            int idx = tid + i * 128;
            int d = idx >> 4, u = idx & 15;
            const size_t gsrc = ((size_t)b * DK + d) * SEQ + k0;
            *reinterpret_cast<uint4*>(&Vhi[d * VSTR + u * 8]) =
                reinterpret_cast<const uint4*>(g_VThi + gsrc)[u];
            *reinterpret_cast<uint4*>(&Vlo[d * VSTR + u * 8]) =
                reinterpret_cast<const uint4*>(g_VTlo + gsrc)[u];
        }
        __syncthreads();

        float sc[16][4];
        #pragma unroll
        for (int i = 0; i < 16; i++)
            #pragma unroll
            for (int j = 0; j < 4; j++) sc[i][j] = 0.0f;

        #pragma unroll
        for (int kb = 0; kb < 4; kb++) {
            #pragma unroll
            for (int pr = 0; pr < 8; pr++) {
                const uint32_t off = (uint32_t)(pr * 16 * KSTR * 2 + kb * 32);
                uint32_t bh[4], bl[4];
                ldsm_x4(bh, khi_base + off);
                ldsm_x4(bl, klo_base + off);
                mma_bf16(sc[pr*2],   qh[kb], bh[0], bh[1]);
                mma_bf16(sc[pr*2],   qh[kb], bl[0], bl[1]);
                mma_bf16(sc[pr*2],   ql[kb], bh[0], bh[1]);
                mma_bf16(sc[pr*2+1], qh[kb], bh[2], bh[3]);
                mma_bf16(sc[pr*2+1], qh[kb], bl[2], bl[3]);
                mma_bf16(sc[pr*2+1], ql[kb], bh[2], bh[3]);
            }
        }

        #pragma unroll
        for (int nb = 0; nb < 16; nb++) {
            const int col0 = k0 + nb * 8 + qc * 2;
            float p0 = (col0     <= rowlo) ? __expf(sc[nb][0]) : 0.0f;
            float p1 = (col0 + 1 <= rowlo) ? __expf(sc[nb][1]) : 0.0f;
            float p2 = (col0     <= rowhi) ? __expf(sc[nb][2]) : 0.0f;
            float p3 = (col0 + 1 <= rowhi) ? __expf(sc[nb][3]) : 0.0f;
            lsum0 += p0 + p1;
            lsum1 += p2 + p3;
            sc[nb][0] = p0; sc[nb][1] = p1; sc[nb][2] = p2; sc[nb][3] = p3;
        }

        #pragma unroll
        for (int kb2 = 0; kb2 < 8; kb2++) {
            uint32_t pah[4], pal[4];
            pah[0] = pack_hi_pair(sc[2*kb2][0],   sc[2*kb2][1]);
            pah[1] = pack_hi_pair(sc[2*kb2][2],   sc[2*kb2][3]);
            pah[2] = pack_hi_pair(sc[2*kb2+1][0], sc[2*kb2+1][1]);
            pah[3] = pack_hi_pair(sc[2*kb2+1][2], sc[2*kb2+1][3]);
            pal[0] = pack_lo_pair(sc[2*kb2][0],   sc[2*kb2][1]);
            pal[1] = pack_lo_pair(sc[2*kb2][2],   sc[2*kb2][3]);
            pal[2] = pack_lo_pair(sc[2*kb2+1][0], sc[2*kb2+1][1]);
            pal[3] = pack_lo_pair(sc[2*kb2+1][2], sc[2*kb2+1][3]);
            #pragma unroll
            for (int pr = 0; pr < 4; pr++) {
                const uint32_t off = (uint32_t)(pr * 16 * VSTR * 2 + kb2 * 32);
                uint32_t bh[4], bl[4];
                ldsm_x4(bh, vhi_base + off);
                ldsm_x4(bl, vlo_base + off);
                mma_bf16(oacc[pr*2],   pah, bh[0], bh[1]);
                mma_bf16(oacc[pr*2],   pah, bl[0], bl[1]);
                mma_bf16(oacc[pr*2],   pal, bh[0], bh[1]);
                mma_bf16(oacc[pr*2+1], pah, bh[2], bh[3]);
                mma_bf16(oacc[pr*2+1], pah, bl[2], bl[3]);
                mma_bf16(oacc[pr*2+1], pal, bh[2], bh[3]);
            }
        }
    }

    lsum0 += __shfl_xor_sync(0xFFFFFFFFu, lsum0, 1);
    lsum0 += __shfl_xor_sync(0xFFFFFFFFu, lsum0, 2);
    lsum1 += __shfl_xor_sync(0xFFFFFFFFu, lsum1, 1);
    lsum1 += __shfl_xor_sync(0xFFFFFFFFu, lsum1, 2);

    const size_t lbase = (size_t)(chunk * BATCH + b) * SEQ + q0 + w * 16;
    if (qc == 0) {
        g_pl[lbase + qr]     = lsum0;
        g_pl[lbase + qr + 8] = lsum1;
    }

    const size_t obase = ((size_t)(chunk * BATCH + b) * SEQ + q0 + w * 16 + qr) * DK;
    #pragma unroll
    for (int db = 0; db < 8; db++) {
        const int n = db * 8 + qc * 2;
        float2 v0, v1;
        v0.x = oacc[db][0]; v0.y = oacc[db][1];
        v1.x = oacc[db][2]; v1.y = oacc[db][3];
        *reinterpret_cast<float2*>(&g_pacc[obase + n]) = v0;
        *reinterpret_cast<float2*>(&g_pacc[obase + 8 * DK + n]) = v1;
    }
}

// ---------------------------------------------------------------------------
// Combine
// ---------------------------------------------------------------------------
__global__ __launch_bounds__(256) void combine_kernel(float* __restrict__ O)
{
    const int idx = blockIdx.x * 256 + threadIdx.x;
    const int qg = idx >> 6;
    const int d  = idx & 63;
    float sa = 0.0f, sl = 0.0f;
    #pragma unroll
    for (int c = 0; c < NCHUNK; c++) {
        sa += g_pacc[((size_t)c * BATCH * SEQ + qg) * DK + d];
        sl += g_pl[(size_t)c * BATCH * SEQ + qg];
    }
    O[idx] = sa / sl;
}

extern "C" void kernel_launch(void* const* d_in, const int* in_sizes, int n_in,
                              void* d_out, int out_size)
{
    const float* qs = (const float*)d_in[0];
    const float* ks = (const float*)d_in[1];
    const float* vs = (const float*)d_in[2];
    // d_in[3] = mask — causal structure handled analytically
    const float* Wq = (const float*)d_in[4];
    const float* bq = (const float*)d_in[5];
    const float* Wk = (const float*)d_in[6];
    const float* bk = (const float*)d_in[7];
    const float* Wv = (const float*)d_in[8];
    const float* bv = (const float*)d_in[9];
    float* out = (float*)d_out;
    (void)in_sizes; (void)n_in; (void)out_size;

    const int proj_smem = 2 * 2 * 64 * WSTR * 2            // W operands 36864
                        + 2 * 128 * XSTG * 4;              // X staging  69632
    const int attn_smem = (2 * 128 * KSTR + 2 * 64 * VSTR) * 2;    // 71680 B
    cudaFuncSetAttribute(proj_mma_kernel, cudaFuncAttributeMaxDynamicSharedMemorySize, proj_smem);
    cudaFuncSetAttribute(attn_mma_kernel, cudaFuncAttributeMaxDynamicSharedMemorySize, attn_smem);

    dim3 wgrid(8, 3);
    w_convert_kernel<<<wgrid, 256>>>(Wq, Wk, Wv);

    dim3 pgrid(128, 3);
    proj_mma_kernel<<<pgrid, 256, proj_smem>>>(qs, ks, vs, bq, bk, bv);

    dim3 agrid(SEQ / 64, NCHUNK, BATCH);
    attn_mma_kernel<<<agrid, 128, attn_smem>>>();

    combine_kernel<<<(BATCH * SEQ * DK) / 256, 256>>>(out);
}

// round 14
// speedup vs baseline: 1.4959x; 1.0233x over previous
#include <cuda_runtime.h>
#include <cuda_bf16.h>
#include <math.h>
#include <stdint.h>

#define DMODEL 512
#define DK     64
#define BATCH  8
#define SEQ    2048
#define NCHUNK 4
#define CHUNK  (SEQ / NCHUNK)   // 512 keys per split-K chunk

// Scratch (device globals — no allocation allowed)
__device__ float g_Q[BATCH * SEQ * DK];                  // pre-scaled by 1/8
__device__ unsigned short g_Khi[BATCH * SEQ * DK];       // bf16 trunc of K
__device__ unsigned short g_Klo[BATCH * SEQ * DK];       // bf16 residual of K
__device__ unsigned short g_VThi[BATCH * DK * SEQ];      // V^T bf16 hi
__device__ unsigned short g_VTlo[BATCH * DK * SEQ];      // V^T bf16 lo
__device__ unsigned short g_Wphi[3 * 8 * 64 * 64];       // W^T bf16 hi [which][kt][n][k]
__device__ unsigned short g_Wplo[3 * 8 * 64 * 64];       // W^T bf16 lo
__device__ float g_pacc[(size_t)NCHUNK * BATCH * SEQ * DK];
__device__ float g_pl[(size_t)NCHUNK * BATCH * SEQ];

// ===================== helpers =====================
__device__ __forceinline__ uint32_t pack_hi_pair(float a, float b) {
    return __byte_perm(__float_as_uint(a), __float_as_uint(b), 0x7632);
}
__device__ __forceinline__ uint32_t pack_lo_pair(float a, float b) {
    float la = a - __uint_as_float(__float_as_uint(a) & 0xFFFF0000u);
    float lb = b - __uint_as_float(__float_as_uint(b) & 0xFFFF0000u);
    uint32_t r;
    asm("cvt.rn.bf16x2.f32 %0, %1, %2;" : "=r"(r) : "f"(lb), "f"(la));
    return r;
}
__device__ __forceinline__ unsigned short hi16(float v) {
    return (unsigned short)(__float_as_uint(v) >> 16);
}
__device__ __forceinline__ unsigned short lo16(float v) {
    float r = v - __uint_as_float(__float_as_uint(v) & 0xFFFF0000u);
    unsigned short s;
    asm("cvt.rn.bf16.f32 %0, %1;" : "=h"(s) : "f"(r));
    return s;
}
__device__ __forceinline__ void mma_bf16(float* c, const uint32_t* a,
                                         uint32_t b0, uint32_t b1) {
    asm volatile(
        "mma.sync.aligned.m16n8k16.row.col.f32.bf16.bf16.f32 "
        "{%0,%1,%2,%3}, {%4,%5,%6,%7}, {%8,%9}, {%0,%1,%2,%3};"
        : "+f"(c[0]), "+f"(c[1]), "+f"(c[2]), "+f"(c[3])
        : "r"(a[0]), "r"(a[1]), "r"(a[2]), "r"(a[3]), "r"(b0), "r"(b1));
}
__device__ __forceinline__ void ldsm_x4(uint32_t* d, uint32_t saddr) {
    asm volatile("ldmatrix.sync.aligned.m8n8.x4.shared.b16 {%0,%1,%2,%3}, [%4];"
                 : "=r"(d[0]), "=r"(d[1]), "=r"(d[2]), "=r"(d[3]) : "r"(saddr));
}
__device__ __forceinline__ uint32_t smem_u32(const void* p) {
    return (uint32_t)__cvta_generic_to_shared(p);
}
__device__ __forceinline__ void cp_async16(uint32_t saddr, const void* gaddr) {
    asm volatile("cp.async.cg.shared.global [%0], [%1], 16;"
                 :: "r"(saddr), "l"(gaddr));
}
#define CP_COMMIT() asm volatile("cp.async.commit_group;" ::: "memory")
#define CP_WAIT0()  asm volatile("cp.async.wait_group 0;" ::: "memory")

// smem strides
#define KSTR 72    // attn K tile rows (bf16 halves), 64-key tiles
#define VSTR2 72   // attn V^T tile rows (64 keys + pad)
#define WSTR 72    // proj W operand rows
#define XSTG 68    // proj X staging stride in FLOATS
#define TSTR 67    // fp32 transpose scratch stride
#define ATILE (64 * KSTR)   // halves per attn operand tile (9216 B)

// ---------------------------------------------------------------------------
// W precompute: W[k][n] fp32 -> g_Wp{hi,lo}[which][kt][n][k] bf16 (B layout)
// ---------------------------------------------------------------------------
__global__ __launch_bounds__(256) void w_convert_kernel(
    const float* __restrict__ Wq, const float* __restrict__ Wk, const float* __restrict__ Wv)
{
    const int kt = blockIdx.x, which = blockIdx.y;
    const float* __restrict__ W = (which == 0) ? Wq : (which == 1) ? Wk : Wv;
    const int base = (which * 8 + kt) * 64 * 64;
    for (int i = 0; i < 16; i++) {
        int e = threadIdx.x + i * 256;
        int n = e >> 6, r = e & 63;
        float v = W[(size_t)(kt * 64 + r) * DK + n];
        g_Wphi[base + n * 64 + r] = hi16(v);
        g_Wplo[base + n * 64 + r] = lo16(v);
    }
}

// ---------------------------------------------------------------------------
// Projection via mma (identical to 111.0us build).
// ---------------------------------------------------------------------------
__global__ __launch_bounds__(256, 2) void proj_mma_kernel(
    const float* __restrict__ Xq, const float* __restrict__ Xk, const float* __restrict__ Xv,
    const float* __restrict__ bq, const float* __restrict__ bk, const float* __restrict__ bv)
{
    extern __shared__ unsigned short psm[];
    unsigned short* Wh = psm;
    unsigned short* Wl = Wh + 2 * 64 * WSTR;
    float* Xs = (float*)(Wl + 2 * 64 * WSTR);

    const int which = blockIdx.y;
    const float* __restrict__ X = (which == 0) ? Xq : (which == 1) ? Xk : Xv;
    const float* __restrict__ bias = (which == 0) ? bq : (which == 1) ? bk : bv;

    const int row0 = blockIdx.x * 128;
    const int tid = threadIdx.x;
    const int w = tid >> 5, lane = tid & 31;
    const int qr = lane >> 2, qc = lane & 3;

    const int b_lrow = ((lane >> 4) & 1) * 8 + (lane & 7);
    const int b_lcol = ((lane >> 3) & 1) * 16;
    const uint32_t wh_base = smem_u32(Wh) + (uint32_t)(b_lrow * WSTR * 2 + b_lcol);
    const uint32_t wl_base = smem_u32(Wl) + (uint32_t)(b_lrow * WSTR * 2 + b_lcol);
    const uint32_t WBUF = (uint32_t)(64 * WSTR * 2);

    const int cr = tid >> 4, cc4 = (tid & 15) * 4;
    const uint32_t xs_s = smem_u32(Xs);
    const uint32_t wh_s = smem_u32(Wh);
    const uint32_t wl_s = smem_u32(Wl);
    const uint32_t xbuf_bytes = (uint32_t)(128 * XSTG * 4);

    float acc[8][4];
    #pragma unroll
    for (int i = 0; i < 8; i++)
        #pragma unroll
        for (int j = 0; j < 4; j++) acc[i][j] = 0.0f;

    const int wgbase = which * 8 * 64 * 64;

    #pragma unroll
    for (int i = 0; i < 8; i++) {
        int r = cr + i * 16;
        cp_async16(xs_s + (uint32_t)((r * XSTG + cc4) * 4),
                   &X[(size_t)(row0 + r) * DMODEL + cc4]);
    }
    #pragma unroll
    for (int i = 0; i < 2; i++) {
        int c = tid + i * 256;
        int n = c >> 3, u = c & 7;
        cp_async16(wh_s + (uint32_t)(n * WSTR * 2 + u * 16),
                   g_Wphi + wgbase + n * 64 + u * 8);
        cp_async16(wl_s + (uint32_t)(n * WSTR * 2 + u * 16),
                   g_Wplo + wgbase + n * 64 + u * 8);
    }
    CP_COMMIT();

    for (int kt = 0; kt < DMODEL / 64; kt++) {
        CP_WAIT0();
        __syncthreads();

        if (kt + 1 < DMODEL / 64) {
            const int k0n = (kt + 1) * 64;
            const uint32_t bsel = (uint32_t)((kt + 1) & 1);
            const uint32_t xdst = xs_s + bsel * xbuf_bytes;
            #pragma unroll
            for (int i = 0; i < 8; i++) {
                int r = cr + i * 16;
                cp_async16(xdst + (uint32_t)((r * XSTG + cc4) * 4),
                           &X[(size_t)(row0 + r) * DMODEL + k0n + cc4]);
            }
            const int wtile = wgbase + (kt + 1) * 64 * 64;
            #pragma unroll
            for (int i = 0; i < 2; i++) {
                int c = tid + i * 256;
                int n = c >> 3, u = c & 7;
                cp_async16(wh_s + bsel * WBUF + (uint32_t)(n * WSTR * 2 + u * 16),
                           g_Wphi + wtile + n * 64 + u * 8);
                cp_async16(wl_s + bsel * WBUF + (uint32_t)(n * WSTR * 2 + u * 16),
                           g_Wplo + wtile + n * 64 + u * 8);
            }
            CP_COMMIT();
        }

        const float* Xc = Xs + (kt & 1) * (128 * XSTG) + (w * 16 + qr) * XSTG;
        const uint32_t wb = (uint32_t)(kt & 1) * WBUF;

        #pragma unroll
        for (int kb = 0; kb < 4; kb++) {
            const int c0 = kb * 16 + qc * 2;
            float2 x00 = *reinterpret_cast<const float2*>(&Xc[c0]);
            float2 x10 = *reinterpret_cast<const float2*>(&Xc[8 * XSTG + c0]);
            float2 x01 = *reinterpret_cast<const float2*>(&Xc[c0 + 8]);
            float2 x11 = *reinterpret_cast<const float2*>(&Xc[8 * XSTG + c0 + 8]);
            uint32_t ah[4], al[4];
            ah[0] = pack_hi_pair(x00.x, x00.y); al[0] = pack_lo_pair(x00.x, x00.y);
            ah[1] = pack_hi_pair(x10.x, x10.y); al[1] = pack_lo_pair(x10.x, x10.y);
            ah[2] = pack_hi_pair(x01.x, x01.y); al[2] = pack_lo_pair(x01.x, x01.y);
            ah[3] = pack_hi_pair(x11.x, x11.y); al[3] = pack_lo_pair(x11.x, x11.y);
            #pragma unroll
            for (int pr = 0; pr < 4; pr++) {
                const uint32_t boff = wb + (uint32_t)(pr * 16 * WSTR * 2 + kb * 32);
                uint32_t bh[4], bl[4];
                ldsm_x4(bh, wh_base + boff);
                ldsm_x4(bl, wl_base + boff);
                mma_bf16(acc[pr*2],   ah, bh[0], bh[1]);
                mma_bf16(acc[pr*2],   ah, bl[0], bl[1]);
                mma_bf16(acc[pr*2],   al, bh[0], bh[1]);
                mma_bf16(acc[pr*2+1], ah, bh[2], bh[3]);
                mma_bf16(acc[pr*2+1], ah, bl[2], bl[3]);
                mma_bf16(acc[pr*2+1], al, bh[2], bh[3]);
            }
        }
    }

    const int r0 = row0 + w * 16 + qr;
    if (which == 2) {
        __syncthreads();
        float* T = Xs;
        const int rl = w * 16 + qr;
        #pragma unroll
        for (int nb = 0; nb < 8; nb++) {
            const int n = nb * 8 + qc * 2;
            float bx = bias[n], by = bias[n + 1];
            T[rl * TSTR + n]           = acc[nb][0] + bx;
            T[rl * TSTR + n + 1]       = acc[nb][1] + by;
            T[(rl + 8) * TSTR + n]     = acc[nb][2] + bx;
            T[(rl + 8) * TSTR + n + 1] = acc[nb][3] + by;
        }
        __syncthreads();
        const int bb = row0 / SEQ, s0 = row0 % SEQ;
        #pragma unroll
        for (int i = 0; i < 16; i++) {
            int idx = tid + i * 256;
            int d = idx >> 6, sp = idx & 63;
            float a = T[(sp * 2) * TSTR + d];
            float c = T[(sp * 2 + 1) * TSTR + d];
            size_t off = ((size_t)bb * DK + d) * SEQ + s0 + sp * 2;
            *(uint32_t*)&g_VThi[off] = pack_hi_pair(a, c);
            *(uint32_t*)&g_VTlo[off] = pack_lo_pair(a, c);
        }
    } else {
        #pragma unroll
        for (int nb = 0; nb < 8; nb++) {
            const int n = nb * 8 + qc * 2;
            float bx = bias[n], by = bias[n + 1];
            float ax = acc[nb][0] + bx, ay = acc[nb][1] + by;
            float cx = acc[nb][2] + bx, cy = acc[nb][3] + by;
            if (which == 1) {
                *(uint32_t*)&g_Khi[(size_t)r0 * DK + n]       = pack_hi_pair(ax, ay);
                *(uint32_t*)&g_Klo[(size_t)r0 * DK + n]       = pack_lo_pair(ax, ay);
                *(uint32_t*)&g_Khi[(size_t)(r0 + 8) * DK + n] = pack_hi_pair(cx, cy);
                *(uint32_t*)&g_Klo[(size_t)(r0 + 8) * DK + n] = pack_lo_pair(cx, cy);
            } else {
                float2 v0, v1;
                v0.x = ax * 0.125f; v0.y = ay * 0.125f;
                v1.x = cx * 0.125f; v1.y = cy * 0.125f;
                *reinterpret_cast<float2*>(&g_Q[(size_t)r0 * DK + n]) = v0;
                *reinterpret_cast<float2*>(&g_Q[(size_t)(r0 + 8) * DK + n]) = v1;
            }
        }
    }
}

// ---------------------------------------------------------------------------
// mma split-K causal attention: 64-key tiles, cp.async double-buffered fills.
// 64 queries/CTA (128 thr, 4 warps). Grid (32, NCHUNK, 8). 3 CTAs/SM.
// ---------------------------------------------------------------------------
__global__ __launch_bounds__(128, 3) void attn_mma_kernel()
{
    extern __shared__ unsigned short asm_[];
    // [buf][array]: Khi, Klo, Vhi, Vlo per buffer, each 64*KSTR halves
    unsigned short* Khi0 = asm_;
    unsigned short* Klo0 = Khi0 + 2 * ATILE;
    unsigned short* Vhi0 = Klo0 + 2 * ATILE;
    unsigned short* Vlo0 = Vhi0 + 2 * ATILE;

    const int qtile = blockIdx.x, chunk = blockIdx.y, b = blockIdx.z;
    const int q0 = qtile * 64;
    const int kbeg = chunk * CHUNK;
    if (kbeg >= q0 + 64) return;
    const int kend = min(kbeg + CHUNK, q0 + 64);
    const int ntiles = (kend - kbeg) >> 6;          // 64-key tiles

    const int tid = threadIdx.x;
    const int w = tid >> 5, lane = tid & 31;
    const int qr = lane >> 2, qc = lane & 3;

    const int lrow = ((lane >> 4) & 1) * 8 + (lane & 7);
    const int lcol = ((lane >> 3) & 1) * 16;
    const uint32_t lsel = (uint32_t)(lrow * KSTR * 2 + lcol);
    const uint32_t khi_s = smem_u32(Khi0), klo_s = smem_u32(Klo0);
    const uint32_t vhi_s = smem_u32(Vhi0), vlo_s = smem_u32(Vlo0);
    const uint32_t ABUF = (uint32_t)(ATILE * 2);    // bytes per tile buffer

    // fill coords: 512 16B-chunks per array, 4 per thread
    const int fr = tid >> 1;                        // unused granular; use idx loop

    // Q fragments (persistent)
    uint32_t qh[4][4], ql[4][4];
    {
        const float* Qp = g_Q + ((size_t)b * SEQ + q0 + w * 16) * DK;
        #pragma unroll
        for (int kb = 0; kb < 4; kb++) {
            const int c0 = kb * 16 + qc * 2;
            float2 x00 = *reinterpret_cast<const float2*>(&Qp[(size_t)qr * DK + c0]);
            float2 x10 = *reinterpret_cast<const float2*>(&Qp[(size_t)(qr + 8) * DK + c0]);
            float2 x01 = *reinterpret_cast<const float2*>(&Qp[(size_t)qr * DK + c0 + 8]);
            float2 x11 = *reinterpret_cast<const float2*>(&Qp[(size_t)(qr + 8) * DK + c0 + 8]);
            qh[kb][0] = pack_hi_pair(x00.x, x00.y); ql[kb][0] = pack_lo_pair(x00.x, x00.y);
            qh[kb][1] = pack_hi_pair(x10.x, x10.y); ql[kb][1] = pack_lo_pair(x10.x, x10.y);
            qh[kb][2] = pack_hi_pair(x01.x, x01.y); ql[kb][2] = pack_lo_pair(x01.x, x01.y);
            qh[kb][3] = pack_hi_pair(x11.x, x11.y); ql[kb][3] = pack_lo_pair(x11.x, x11.y);
        }
    }

    float oacc[8][4];
    #pragma unroll
    for (int i = 0; i < 8; i++)
        #pragma unroll
        for (int j = 0; j < 4; j++) oacc[i][j] = 0.0f;
    float lsum0 = 0.0f, lsum1 = 0.0f;

    const int rowlo = q0 + w * 16 + qr;
    const int rowhi = rowlo + 8;

    // stage tile 0 into buffer 0
    {
        const int k0 = kbeg;
        #pragma unroll
        for (int i = 0; i < 4; i++) {
            int idx = tid + i * 128;                // 0..511
            int row = idx >> 3, u = idx & 7;
            uint32_t doff = (uint32_t)(row * KSTR * 2 + u * 16);
            cp_async16(khi_s + doff, g_Khi + ((size_t)b * SEQ + k0 + row) * DK + u * 8);
            cp_async16(klo_s + doff, g_Klo + ((size_t)b * SEQ + k0 + row) * DK + u * 8);
            cp_async16(vhi_s + doff, g_VThi + ((size_t)b * DK + row) * SEQ + k0 + u * 8);
            cp_async16(vlo_s + doff, g_VTlo + ((size_t)b * DK + row) * SEQ + k0 + u * 8);
        }
        CP_COMMIT();
    }

    for (int t = 0; t < ntiles; t++) {
        const int k0 = kbeg + t * 64;
        CP_WAIT0();
        __syncthreads();

        // stage tile t+1 into other buffer while computing t
        if (t + 1 < ntiles) {
            const int k0n = k0 + 64;
            const uint32_t boffs = (uint32_t)((t + 1) & 1) * ABUF;
            #pragma unroll
            for (int i = 0; i < 4; i++) {
                int idx = tid + i * 128;
                int row = idx >> 3, u = idx & 7;
                uint32_t doff = boffs + (uint32_t)(row * KSTR * 2 + u * 16);
                cp_async16(khi_s + doff, g_Khi + ((size_t)b * SEQ + k0n + row) * DK + u * 8);
                cp_async16(klo_s + doff, g_Klo + ((size_t)b * SEQ + k0n + row) * DK + u * 8);
                cp_async16(vhi_s + doff, g_VThi + ((size_t)b * DK + row) * SEQ + k0n + u * 8);
                cp_async16(vlo_s + doff, g_VTlo + ((size_t)b * DK + row) * SEQ + k0n + u * 8);
            }
            CP_COMMIT();
        }

        const uint32_t cb = (uint32_t)(t & 1) * ABUF;
        const uint32_t khi_base = khi_s + cb + lsel;
        const uint32_t klo_base = klo_s + cb + lsel;
        const uint32_t vhi_base = vhi_s + cb + lsel;
        const uint32_t vlo_base = vlo_s + cb + lsel;

        // ---- S = Q K^T (8 n-blocks of 8 keys) ----
        float sc[8][4];
        #pragma unroll
        for (int i = 0; i < 8; i++)
            #pragma unroll
            for (int j = 0; j < 4; j++) sc[i][j] = 0.0f;

        #pragma unroll
        for (int kb = 0; kb < 4; kb++) {
            #pragma unroll
            for (int pr = 0; pr < 4; pr++) {
                const uint32_t off = (uint32_t)(pr * 16 * KSTR * 2 + kb * 32);
                uint32_t bh[4], bl[4];
                ldsm_x4(bh, khi_base + off);
                ldsm_x4(bl, klo_base + off);
                mma_bf16(sc[pr*2],   qh[kb], bh[0], bh[1]);
                mma_bf16(sc[pr*2],   qh[kb], bl[0], bl[1]);
                mma_bf16(sc[pr*2],   ql[kb], bh[0], bh[1]);
                mma_bf16(sc[pr*2+1], qh[kb], bh[2], bh[3]);
                mma_bf16(sc[pr*2+1], qh[kb], bl[2], bl[3]);
                mma_bf16(sc[pr*2+1], ql[kb], bh[2], bh[3]);
            }
        }

        // ---- p = mask ? exp(s) : 0 ----
        #pragma unroll
        for (int nb = 0; nb < 8; nb++) {
            const int col0 = k0 + nb * 8 + qc * 2;
            float p0 = (col0     <= rowlo) ? __expf(sc[nb][0]) : 0.0f;
            float p1 = (col0 + 1 <= rowlo) ? __expf(sc[nb][1]) : 0.0f;
            float p2 = (col0     <= rowhi) ? __expf(sc[nb][2]) : 0.0f;
            float p3 = (col0 + 1 <= rowhi) ? __expf(sc[nb][3]) : 0.0f;
            lsum0 += p0 + p1;
            lsum1 += p2 + p3;
            sc[nb][0] = p0; sc[nb][1] = p1; sc[nb][2] = p2; sc[nb][3] = p3;
        }

        // ---- O += P V (4 k-blocks of 16 keys) ----
        #pragma unroll
        for (int kb2 = 0; kb2 < 4; kb2++) {
            uint32_t pah[4], pal[4];
            pah[0] = pack_hi_pair(sc[2*kb2][0],   sc[2*kb2][1]);
            pah[1] = pack_hi_pair(sc[2*kb2][2],   sc[2*kb2][3]);
            pah[2] = pack_hi_pair(sc[2*kb2+1][0], sc[2*kb2+1][1]);
            pah[3] = pack_hi_pair(sc[2*kb2+1][2], sc[2*kb2+1][3]);
            pal[0] = pack_lo_pair(sc[2*kb2][0],   sc[2*kb2][1]);
            pal[1] = pack_lo_pair(sc[2*kb2][2],   sc[2*kb2][3]);
            pal[2] = pack_lo_pair(sc[2*kb2+1][0], sc[2*kb2+1][1]);
            pal[3] = pack_lo_pair(sc[2*kb2+1][2], sc[2*kb2+1][3]);
            #pragma unroll
            for (int pr = 0; pr < 4; pr++) {
                const uint32_t off = (uint32_t)(pr * 16 * KSTR * 2 + kb2 * 32);
                uint32_t bh[4], bl[4];
                ldsm_x4(bh, vhi_base + off);
                ldsm_x4(bl, vlo_base + off);
                mma_bf16(oacc[pr*2],   pah, bh[0], bh[1]);
                mma_bf16(oacc[pr*2],   pah, bl[0], bl[1]);
                mma_bf16(oacc[pr*2],   pal, bh[0], bh[1]);
                mma_bf16(oacc[pr*2+1], pah, bh[2], bh[3]);
                mma_bf16(oacc[pr*2+1], pah, bl[2], bl[3]);
                mma_bf16(oacc[pr*2+1], pal, bh[2], bh[3]);
            }
        }
    }

    lsum0 += __shfl_xor_sync(0xFFFFFFFFu, lsum0, 1);
    lsum0 += __shfl_xor_sync(0xFFFFFFFFu, lsum0, 2);
    lsum1 += __shfl_xor_sync(0xFFFFFFFFu, lsum1, 1);
    lsum1 += __shfl_xor_sync(0xFFFFFFFFu, lsum1, 2);

    const size_t lbase = (size_t)(chunk * BATCH + b) * SEQ + q0 + w * 16;
    if (qc == 0) {
        g_pl[lbase + qr]     = lsum0;
        g_pl[lbase + qr + 8] = lsum1;
    }

    const size_t obase = ((size_t)(chunk * BATCH + b) * SEQ + q0 + w * 16 + qr) * DK;
    #pragma unroll
    for (int db = 0; db < 8; db++) {
        const int n = db * 8 + qc * 2;
        float2 v0, v1;
        v0.x = oacc[db][0]; v0.y = oacc[db][1];
        v1.x = oacc[db][2]; v1.y = oacc[db][3];
        *reinterpret_cast<float2*>(&g_pacc[obase + n]) = v0;
        *reinterpret_cast<float2*>(&g_pacc[obase + 8 * DK + n]) = v1;
    }
    (void)fr;
}

// ---------------------------------------------------------------------------
// Combine
// ---------------------------------------------------------------------------
__global__ __launch_bounds__(256) void combine_kernel(float* __restrict__ O)
{
    const int idx = blockIdx.x * 256 + threadIdx.x;
    const int qg = idx >> 6;
    const int d  = idx & 63;
    float sa = 0.0f, sl = 0.0f;
    #pragma unroll
    for (int c = 0; c < NCHUNK; c++) {
        sa += g_pacc[((size_t)c * BATCH * SEQ + qg) * DK + d];
        sl += g_pl[(size_t)c * BATCH * SEQ + qg];
    }
    O[idx] = sa / sl;
}

extern "C" void kernel_launch(void* const* d_in, const int* in_sizes, int n_in,
                              void* d_out, int out_size)
{
    const float* qs = (const float*)d_in[0];
    const float* ks = (const float*)d_in[1];
    const float* vs = (const float*)d_in[2];
    // d_in[3] = mask — causal structure handled analytically
    const float* Wq = (const float*)d_in[4];
    const float* bq = (const float*)d_in[5];
    const float* Wk = (const float*)d_in[6];
    const float* bk = (const float*)d_in[7];
    const float* Wv = (const float*)d_in[8];
    const float* bv = (const float*)d_in[9];
    float* out = (float*)d_out;
    (void)in_sizes; (void)n_in; (void)out_size;

    const int proj_smem = 2 * 2 * 64 * WSTR * 2            // W operands 36864
                        + 2 * 128 * XSTG * 4;              // X staging  69632
    const int attn_smem = 8 * ATILE * 2;                   // 73728 B (2 bufs x 4 arrays)
    cudaFuncSetAttribute(proj_mma_kernel, cudaFuncAttributeMaxDynamicSharedMemorySize, proj_smem);
    cudaFuncSetAttribute(attn_mma_kernel, cudaFuncAttributeMaxDynamicSharedMemorySize, attn_smem);

    dim3 wgrid(8, 3);
    w_convert_kernel<<<wgrid, 256>>>(Wq, Wk, Wv);

    dim3 pgrid(128, 3);
    proj_mma_kernel<<<pgrid, 256, proj_smem>>>(qs, ks, vs, bq, bk, bv);

    dim3 agrid(SEQ / 64, NCHUNK, BATCH);
    attn_mma_kernel<<<agrid, 128, attn_smem>>>();

    combine_kernel<<<(BATCH * SEQ * DK) / 256, 256>>>(out);
}